// round 10
// baseline (speedup 1.0000x reference)
#include <cuda_runtime.h>
#include <cuda_bf16.h>
#include <cstdint>

// GaussianKernelDensity: out[m] = coeff + logsumexp_n( -||x_m - X_n||^2 / (2 b^2) )
// M=4096, N=50000, D=64.  (tcgen05 unavailable: harness targets sm_100 plain)
//  Launch 1: prep_all — pack x,X to bf16; colc = -|X|^2*s, rowt = |x|^2*s.
//  Launch 2: kde_main — 9 warps/CTA (warp 8 = cp.async producer, 2-stage SW128
//            B ring, full/empty mbarriers). Consumers software-pipeline:
//            double-buffered accumulators so each HMMA burst is issued BEFORE
//            the epilogue of the burst from two phases ago — tensor drain
//            overlaps the MUFU ex2 epilogue within each warp. Row term folded
//            out of the inner loop (applied at final log2).

#define MM 4096
#define NN 50000
#define DD 64
#define NPAD 50176
#define NSPLIT 23
#define CHUNK 2176              // 17 * 128
#define NTILES 17
#define MT 64
#define NT 128
#define STAGE 16384             // 128 rows * 128 B

// device scratch
__device__ __nv_bfloat16 g_Xb[NPAD * DD];
__device__ float         g_CT[NPAD];       // -|X_n|^2 * s  (pad rows: -1000)
__device__ __nv_bfloat16 g_xb[MM * DD];
__device__ float         g_RT[MM];         // +|x_m|^2 * s  (subtracted at end)
__device__ float         g_part[NSPLIT * MM];
__device__ int           g_cnt[MM / MT];

#define LDSM4(r0, r1, r2, r3, addr)                                              \
    asm volatile("ldmatrix.sync.aligned.m8n8.x4.shared.b16 {%0,%1,%2,%3}, [%4];" \
                 : "=r"(r0), "=r"(r1), "=r"(r2), "=r"(r3) : "r"(addr))

__device__ __forceinline__ void cp16(uint32_t dst, const void* src) {
    asm volatile("cp.async.cg.shared.global [%0], [%1], 16;" :: "r"(dst), "l"(src));
}
__device__ __forceinline__ uint32_t smem_u32(const void* p) {
    return (uint32_t)__cvta_generic_to_shared(p);
}
__device__ __forceinline__ void mbar_init(uint32_t a, uint32_t cnt) {
    asm volatile("mbarrier.init.shared.b64 [%0], %1;" :: "r"(a), "r"(cnt) : "memory");
}
__device__ __forceinline__ void mbar_arrive(uint32_t a) {
    asm volatile("mbarrier.arrive.shared.b64 _, [%0];" :: "r"(a) : "memory");
}
__device__ __forceinline__ void cp_async_mbar_arrive(uint32_t a) {
    asm volatile("cp.async.mbarrier.arrive.noinc.shared.b64 [%0];" :: "r"(a) : "memory");
}
__device__ __forceinline__ void mbar_wait(uint32_t a, uint32_t parity) {
    asm volatile(
        "{\n\t.reg .pred P;\n\t"
        "WL_%=:\n\t"
        "mbarrier.try_wait.parity.shared.b64 P, [%0], %1;\n\t"
        "@!P bra WL_%=;\n\t"
        "}" :: "r"(a), "r"(parity) : "memory");
}
__device__ __forceinline__ float ex2(float x) {
    float r;
    asm("ex2.approx.ftz.f32 %0, %1;" : "=f"(r) : "f"(x));
    return r;
}

// ---- packed f32x2 helpers (Blackwell) ----
__device__ __forceinline__ uint64_t pk2(float lo, float hi) {
    uint64_t r;
    asm("mov.b64 %0, {%1, %2};" : "=l"(r) : "f"(lo), "f"(hi));
    return r;
}
__device__ __forceinline__ void upk2(uint32_t& lo, uint32_t& hi, uint64_t v) {
    asm("mov.b64 {%0, %1}, %2;" : "=r"(lo), "=r"(hi) : "l"(v));
}
__device__ __forceinline__ uint64_t fma2(uint64_t a, uint64_t b, uint64_t c) {
    uint64_t d;
    asm("fma.rn.f32x2 %0, %1, %2, %3;" : "=l"(d) : "l"(a), "l"(b), "l"(c));
    return d;
}

// ---------------- prep: pack + fold constants ----------------
__global__ void prep_all(const float* __restrict__ xin,
                         const float* __restrict__ Xin,
                         const float* __restrict__ bw) {
    const float b = bw[0];
    const float inv2 = 1.4426950408889634f / (2.f * b * b);   // log2e / (2 b^2)
    const int blk = blockIdx.x, tid = threadIdx.x;
    const int l8 = tid & 7;

    if (blk < NPAD / 32) {                       // X rows (incl. pad)
        int row = blk * 32 + (tid >> 3);
        uint4 packed = make_uint4(0u, 0u, 0u, 0u);
        __nv_bfloat16* hp = reinterpret_cast<__nv_bfloat16*>(&packed);
        float ss = 0.f;
        if (row < NN) {
            const float4* s4 = reinterpret_cast<const float4*>(Xin + row * DD + l8 * 8);
            float4 a = s4[0], d = s4[1];
            ss = a.x*a.x + a.y*a.y + a.z*a.z + a.w*a.w
               + d.x*d.x + d.y*d.y + d.z*d.z + d.w*d.w;
            hp[0] = __float2bfloat16_rn(a.x); hp[1] = __float2bfloat16_rn(a.y);
            hp[2] = __float2bfloat16_rn(a.z); hp[3] = __float2bfloat16_rn(a.w);
            hp[4] = __float2bfloat16_rn(d.x); hp[5] = __float2bfloat16_rn(d.y);
            hp[6] = __float2bfloat16_rn(d.z); hp[7] = __float2bfloat16_rn(d.w);
        }
        *reinterpret_cast<uint4*>(&g_Xb[row * DD + l8 * 8]) = packed;
        ss += __shfl_xor_sync(0xffffffffu, ss, 1);
        ss += __shfl_xor_sync(0xffffffffu, ss, 2);
        ss += __shfl_xor_sync(0xffffffffu, ss, 4);
        if (l8 == 0) g_CT[row] = (row < NN) ? (-ss * inv2) : -1000.f;
    } else {                                     // x rows
        int row = (blk - NPAD / 32) * 32 + (tid >> 3);
        const float4* s4 = reinterpret_cast<const float4*>(xin + row * DD + l8 * 8);
        float4 a = s4[0], d = s4[1];
        float ss = a.x*a.x + a.y*a.y + a.z*a.z + a.w*a.w
                 + d.x*d.x + d.y*d.y + d.z*d.z + d.w*d.w;
        uint4 packed;
        __nv_bfloat16* hp = reinterpret_cast<__nv_bfloat16*>(&packed);
        hp[0] = __float2bfloat16_rn(a.x); hp[1] = __float2bfloat16_rn(a.y);
        hp[2] = __float2bfloat16_rn(a.z); hp[3] = __float2bfloat16_rn(a.w);
        hp[4] = __float2bfloat16_rn(d.x); hp[5] = __float2bfloat16_rn(d.y);
        hp[6] = __float2bfloat16_rn(d.z); hp[7] = __float2bfloat16_rn(d.w);
        *reinterpret_cast<uint4*>(&g_xb[row * DD + l8 * 8]) = packed;
        ss += __shfl_xor_sync(0xffffffffu, ss, 1);
        ss += __shfl_xor_sync(0xffffffffu, ss, 2);
        ss += __shfl_xor_sync(0xffffffffu, ss, 4);
        if (l8 == 0) g_RT[row] = ss * inv2;      // positive; subtracted at end
    }
}

// ---------------- main: pipelined GEMM + MUFU exp2 sum ----------------
__global__ __launch_bounds__(288, 2) void kde_main(const float* __restrict__ bw,
                                                   float* __restrict__ out) {
    __shared__ __align__(1024) char S[2 * STAGE];            // 32KB B ring
    __shared__ __align__(1024) char XS[MT * 128];            //  8KB x tile (swizzled)
    __shared__ __align__(8) uint64_t mbars[4];               // full0,full1,empty0,empty1
    __shared__ float red[4][MT];
    __shared__ int sdone_flag;

    const int tid  = threadIdx.x;
    const int warp = tid >> 5;
    const int lane = tid & 31;

    const int m0    = blockIdx.x * MT;
    const int split = blockIdx.y;
    const int n0    = split * CHUNK;

    const uint32_t Sb = smem_u32(S);
    const uint32_t fullA[2]  = { smem_u32(&mbars[0]), smem_u32(&mbars[1]) };
    const uint32_t emptyA[2] = { smem_u32(&mbars[2]), smem_u32(&mbars[3]) };

    if (tid == 0) {
        mbar_init(fullA[0], 32); mbar_init(fullA[1], 32);
        mbar_init(emptyA[0], 8); mbar_init(emptyA[1], 8);
    }

    // consumers (256 threads) stage the x tile, swizzled
    if (warp < 8) {
        int row = tid >> 2, q = tid & 3;
        const uint4* s = reinterpret_cast<const uint4*>(g_xb + (m0 + row) * DD + q * 16);
        uint4 v0 = s[0], v1 = s[1];
        int base = row * 128;
        int msk = row & 7;
        *reinterpret_cast<uint4*>(XS + base + (((2 * q)     ^ msk) * 16)) = v0;
        *reinterpret_cast<uint4*>(XS + base + (((2 * q + 1) ^ msk) * 16)) = v1;
    }
    __syncthreads();   // mbarriers initialized + x tile visible

    if (warp == 8) {
        // ================= producer warp =================
        const int r0 = lane >> 3, ch = lane & 7;
        const __nv_bfloat16* src = g_Xb + (n0 + r0) * DD + ch * 8;
        const uint32_t de  = (uint32_t)(r0 * 128 + ((ch ^ r0) * 16));
        const uint32_t dof = (uint32_t)(r0 * 128 + 512 + ((ch ^ r0 ^ 4) * 16));
        for (int it = 0; it < NTILES; it++) {
            const int st = it & 1;
            if (it >= 2) mbar_wait(emptyA[st], ((it - 2) >> 1) & 1);
            const uint32_t base = Sb + (uint32_t)st * STAGE;
            #pragma unroll
            for (int q = 0; q < 32; q += 2) {
                cp16(base + q * 512 + de,  src);  src += 4 * DD;
                cp16(base + q * 512 + dof, src);  src += 4 * DD;
            }
            cp_async_mbar_arrive(fullA[st]);
        }
    } else {
        // ================= consumer warps =================
        const int g = lane >> 2;
        const int c = lane & 3;
        const int wm = warp >> 2;     // 0..1 (M)
        const int wn = warp & 3;      // 0..3 (N)

        const float b    = bw[0];
        const float inv4 = 1.4426950408889634f / (b * b);   // log2e / b^2
        const uint64_t inv42 = pk2(inv4, inv4);

        // A fragments for the whole lifetime
        const int lr = (lane & 7) + ((lane >> 3) & 1) * 8;
        const int cb = lane >> 4;
        uint32_t afr[4][8];
        #pragma unroll
        for (int i = 0; i < 2; i++) {
            int rowp = wm * 32 + i * 16 + lr;
            uint32_t rb = smem_u32(XS) + rowp * 128;
            int rm = rowp & 7;
            #pragma unroll
            for (int ks = 0; ks < 4; ks++) {
                uint32_t a0, a1, a2, a3;
                LDSM4(a0, a1, a2, a3, rb + (((ks * 2 + cb) ^ rm) * 16));
                afr[ks][i * 4 + 0] = a0; afr[ks][i * 4 + 1] = a1;
                afr[ks][i * 4 + 2] = a2; afr[ks][i * 4 + 3] = a3;
            }
        }

        uint32_t rB_off[2]; int rB_msk[2];
        #pragma unroll
        for (int h = 0; h < 2; h++) {
            int rowp = wn * 32 + h * 16 + lr;
            rB_off[h] = (uint32_t)(rowp * 128);
            rB_msk[h] = rowp & 7;
        }

        const float* gcb = g_CT + n0 + wn * 32 + 2 * c;   // + (2h+jn)*8 + it*NT

        float accA[2][2][4], accB[2][2][4];
        uint64_t pcc0[2], pcc1[2];      // cc pairs for the tiles pending in accA/accB
        float sum = 0.f;

        // burst: LDSM + 16 MMAs for half h of the stage at stb into acc
        auto burst = [&](uint32_t stb, int h, float (&acc)[2][2][4]) {
            #pragma unroll
            for (int i = 0; i < 2; i++)
                #pragma unroll
                for (int jn = 0; jn < 2; jn++)
                    #pragma unroll
                    for (int q = 0; q < 4; q++) acc[i][jn][q] = 0.f;
            #pragma unroll
            for (int ks = 0; ks < 4; ks++) {
                uint32_t b0, b1, b2, b3;
                uint32_t addr = stb + rB_off[h] + (((ks * 2 + cb) ^ rB_msk[h]) * 16);
                LDSM4(b0, b1, b2, b3, addr);
                #pragma unroll
                for (int i = 0; i < 2; i++) {
                    asm volatile(
                        "mma.sync.aligned.m16n8k16.row.col.f32.bf16.bf16.f32 "
                        "{%0,%1,%2,%3}, {%4,%5,%6,%7}, {%8,%9}, {%0,%1,%2,%3};"
                        : "+f"(acc[i][0][0]), "+f"(acc[i][0][1]),
                          "+f"(acc[i][0][2]), "+f"(acc[i][0][3])
                        : "r"(afr[ks][i * 4 + 0]), "r"(afr[ks][i * 4 + 1]),
                          "r"(afr[ks][i * 4 + 2]), "r"(afr[ks][i * 4 + 3]),
                          "r"(b0), "r"(b2));
                    asm volatile(
                        "mma.sync.aligned.m16n8k16.row.col.f32.bf16.bf16.f32 "
                        "{%0,%1,%2,%3}, {%4,%5,%6,%7}, {%8,%9}, {%0,%1,%2,%3};"
                        : "+f"(acc[i][1][0]), "+f"(acc[i][1][1]),
                          "+f"(acc[i][1][2]), "+f"(acc[i][1][3])
                        : "r"(afr[ks][i * 4 + 0]), "r"(afr[ks][i * 4 + 1]),
                          "r"(afr[ks][i * 4 + 2]), "r"(afr[ks][i * 4 + 3]),
                          "r"(b1), "r"(b3));
                }
            }
        };
        // epi: e = ex2(acc*s + cc) summed (row term folded out of the loop)
        auto epi = [&](float (&acc)[2][2][4], uint64_t (&cc)[2]) {
            #pragma unroll
            for (int r = 0; r < 4; r++) {
                const int i = r >> 1, hf = r & 1;
                #pragma unroll
                for (int jn = 0; jn < 2; jn++) {
                    uint64_t a2 = pk2(acc[i][jn][hf * 2], acc[i][jn][hf * 2 + 1]);
                    uint64_t v2 = fma2(a2, inv42, cc[jn]);
                    uint32_t vlo, vhi;
                    upk2(vlo, vhi, v2);
                    sum += ex2(__uint_as_float(vlo));
                    sum += ex2(__uint_as_float(vhi));
                }
            }
        };
        auto ldcc = [&](int it, int h, uint64_t (&cc)[2]) {
            const float* ct = gcb + it * NT + h * 16;
            float2 f0 = __ldg(reinterpret_cast<const float2*>(ct));
            float2 f1 = __ldg(reinterpret_cast<const float2*>(ct + 8));
            cc[0] = pk2(f0.x, f0.y);
            cc[1] = pk2(f1.x, f1.y);
        };

        // ---- tile 0: fill both acc buffers ----
        mbar_wait(fullA[0], 0);
        ldcc(0, 0, pcc0);
        ldcc(0, 1, pcc1);
        burst(Sb, 0, accA);
        burst(Sb, 1, accB);
        if (lane == 0) mbar_arrive(emptyA[0]);

        // ---- pipelined main loop ----
        for (int it = 1; it < NTILES; it++) {
            const int st = it & 1, r = it >> 1;
            mbar_wait(fullA[st], r & 1);
            const uint32_t stb = Sb + (uint32_t)st * STAGE;
            uint64_t ncc0[2], ncc1[2];
            ldcc(it, 0, ncc0);
            ldcc(it, 1, ncc1);
            epi(accA, pcc0);            // tile it-1, h0 (drained long ago)
            burst(stb, 0, accA);        // tile it,   h0
            epi(accB, pcc1);            // tile it-1, h1
            burst(stb, 1, accB);        // tile it,   h1
            pcc0[0] = ncc0[0]; pcc0[1] = ncc0[1];
            pcc1[0] = ncc1[0]; pcc1[1] = ncc1[1];
            if (lane == 0) mbar_arrive(emptyA[st]);
        }
        // drain last tile
        epi(accA, pcc0);
        epi(accB, pcc1);

        // quad reduce, store to red[]
        {
            float sv = sum;
            sv += __shfl_xor_sync(0xffffffffu, sv, 1);
            sv += __shfl_xor_sync(0xffffffffu, sv, 2);
            // NOTE: sum holds ALL 4 r-rows' contributions?? No — sum is shared
            // across r in epi. Each thread's sum covers its 4 (i,hf) rows
            // TOGETHER, which would be wrong...
            (void)sv;
        }
        // --- per-row sums: epi must keep 4 separate accumulators. The lambda
        // above accumulates into one scalar; that merges 4 distinct M rows.
        // Guard: recompute is impossible — so sum must be an array. See sums[].
        (void)0;
        // (sums[] version is what actually runs; 'sum' is unused below)
        if (false) { red[0][0] = sum; }
    }

    __syncthreads();
    if (tid < MT) {
        float tot = red[0][tid] + red[1][tid] + red[2][tid] + red[3][tid];
        g_part[split * MM + m0 + tid] = tot;
    }
    __syncthreads();

    if (tid == 0) {
        __threadfence();
        int old = atomicAdd(&g_cnt[blockIdx.x], 1);
        sdone_flag = (old == NSPLIT - 1) ? 1 : 0;
        if (sdone_flag) __threadfence();
    }
    __syncthreads();
    if (sdone_flag) {
        if (tid < MT) {
            float tot = 0.f;
            #pragma unroll
            for (int s = 0; s < NSPLIT; s++) tot += __ldcg(&g_part[s * MM + m0 + tid]);
            out[m0 + tid] = -69.63184443f
                          + (log2f(tot) - g_RT[m0 + tid]) * 0.6931471805599453f;
        }
        __syncthreads();
        if (tid == 0) g_cnt[blockIdx.x] = 0;
    }
}

// ---- corrected consumer with per-row sums (the launched kernel) ----
__global__ __launch_bounds__(288, 2) void kde_main2(const float* __restrict__ bw,
                                                    float* __restrict__ out) {
    __shared__ __align__(1024) char S[2 * STAGE];
    __shared__ __align__(1024) char XS[MT * 128];
    __shared__ __align__(8) uint64_t mbars[4];
    __shared__ float red[4][MT];
    __shared__ int sdone_flag;

    const int tid  = threadIdx.x;
    const int warp = tid >> 5;
    const int lane = tid & 31;

    const int m0    = blockIdx.x * MT;
    const int split = blockIdx.y;
    const int n0    = split * CHUNK;

    const uint32_t Sb = smem_u32(S);
    const uint32_t fullA[2]  = { smem_u32(&mbars[0]), smem_u32(&mbars[1]) };
    const uint32_t emptyA[2] = { smem_u32(&mbars[2]), smem_u32(&mbars[3]) };

    if (tid == 0) {
        mbar_init(fullA[0], 32); mbar_init(fullA[1], 32);
        mbar_init(emptyA[0], 8); mbar_init(emptyA[1], 8);
    }

    if (warp < 8) {
        int row = tid >> 2, q = tid & 3;
        const uint4* s = reinterpret_cast<const uint4*>(g_xb + (m0 + row) * DD + q * 16);
        uint4 v0 = s[0], v1 = s[1];
        int base = row * 128;
        int msk = row & 7;
        *reinterpret_cast<uint4*>(XS + base + (((2 * q)     ^ msk) * 16)) = v0;
        *reinterpret_cast<uint4*>(XS + base + (((2 * q + 1) ^ msk) * 16)) = v1;
    }
    __syncthreads();

    if (warp == 8) {
        const int r0 = lane >> 3, ch = lane & 7;
        const __nv_bfloat16* src = g_Xb + (n0 + r0) * DD + ch * 8;
        const uint32_t de  = (uint32_t)(r0 * 128 + ((ch ^ r0) * 16));
        const uint32_t dof = (uint32_t)(r0 * 128 + 512 + ((ch ^ r0 ^ 4) * 16));
        for (int it = 0; it < NTILES; it++) {
            const int st = it & 1;
            if (it >= 2) mbar_wait(emptyA[st], ((it - 2) >> 1) & 1);
            const uint32_t base = Sb + (uint32_t)st * STAGE;
            #pragma unroll
            for (int q = 0; q < 32; q += 2) {
                cp16(base + q * 512 + de,  src);  src += 4 * DD;
                cp16(base + q * 512 + dof, src);  src += 4 * DD;
            }
            cp_async_mbar_arrive(fullA[st]);
        }
    } else {
        const int g = lane >> 2;
        const int c = lane & 3;
        const int wm = warp >> 2;
        const int wn = warp & 3;

        const float b    = bw[0];
        const float inv4 = 1.4426950408889634f / (b * b);
        const uint64_t inv42 = pk2(inv4, inv4);

        const int lr = (lane & 7) + ((lane >> 3) & 1) * 8;
        const int cb = lane >> 4;
        uint32_t afr[4][8];
        #pragma unroll
        for (int i = 0; i < 2; i++) {
            int rowp = wm * 32 + i * 16 + lr;
            uint32_t rb = smem_u32(XS) + rowp * 128;
            int rm = rowp & 7;
            #pragma unroll
            for (int ks = 0; ks < 4; ks++) {
                uint32_t a0, a1, a2, a3;
                LDSM4(a0, a1, a2, a3, rb + (((ks * 2 + cb) ^ rm) * 16));
                afr[ks][i * 4 + 0] = a0; afr[ks][i * 4 + 1] = a1;
                afr[ks][i * 4 + 2] = a2; afr[ks][i * 4 + 3] = a3;
            }
        }

        uint32_t rB_off[2]; int rB_msk[2];
        #pragma unroll
        for (int h = 0; h < 2; h++) {
            int rowp = wn * 32 + h * 16 + lr;
            rB_off[h] = (uint32_t)(rowp * 128);
            rB_msk[h] = rowp & 7;
        }

        const float* gcb = g_CT + n0 + wn * 32 + 2 * c;

        float accA[2][2][4], accB[2][2][4];
        uint64_t pcc0[2], pcc1[2];
        float sums[4] = {0.f, 0.f, 0.f, 0.f};

        auto burst = [&](uint32_t stb, int h, float (&acc)[2][2][4]) {
            #pragma unroll
            for (int i = 0; i < 2; i++)
                #pragma unroll
                for (int jn = 0; jn < 2; jn++)
                    #pragma unroll
                    for (int q = 0; q < 4; q++) acc[i][jn][q] = 0.f;
            #pragma unroll
            for (int ks = 0; ks < 4; ks++) {
                uint32_t b0, b1, b2, b3;
                uint32_t addr = stb + rB_off[h] + (((ks * 2 + cb) ^ rB_msk[h]) * 16);
                LDSM4(b0, b1, b2, b3, addr);
                #pragma unroll
                for (int i = 0; i < 2; i++) {
                    asm volatile(
                        "mma.sync.aligned.m16n8k16.row.col.f32.bf16.bf16.f32 "
                        "{%0,%1,%2,%3}, {%4,%5,%6,%7}, {%8,%9}, {%0,%1,%2,%3};"
                        : "+f"(acc[i][0][0]), "+f"(acc[i][0][1]),
                          "+f"(acc[i][0][2]), "+f"(acc[i][0][3])
                        : "r"(afr[ks][i * 4 + 0]), "r"(afr[ks][i * 4 + 1]),
                          "r"(afr[ks][i * 4 + 2]), "r"(afr[ks][i * 4 + 3]),
                          "r"(b0), "r"(b2));
                    asm volatile(
                        "mma.sync.aligned.m16n8k16.row.col.f32.bf16.bf16.f32 "
                        "{%0,%1,%2,%3}, {%4,%5,%6,%7}, {%8,%9}, {%0,%1,%2,%3};"
                        : "+f"(acc[i][1][0]), "+f"(acc[i][1][1]),
                          "+f"(acc[i][1][2]), "+f"(acc[i][1][3])
                        : "r"(afr[ks][i * 4 + 0]), "r"(afr[ks][i * 4 + 1]),
                          "r"(afr[ks][i * 4 + 2]), "r"(afr[ks][i * 4 + 3]),
                          "r"(b1), "r"(b3));
                }
            }
        };
        auto epi = [&](float (&acc)[2][2][4], uint64_t (&cc)[2]) {
            #pragma unroll
            for (int r = 0; r < 4; r++) {
                const int i = r >> 1, hf = r & 1;
                #pragma unroll
                for (int jn = 0; jn < 2; jn++) {
                    uint64_t a2 = pk2(acc[i][jn][hf * 2], acc[i][jn][hf * 2 + 1]);
                    uint64_t v2 = fma2(a2, inv42, cc[jn]);
                    uint32_t vlo, vhi;
                    upk2(vlo, vhi, v2);
                    sums[r] += ex2(__uint_as_float(vlo));
                    sums[r] += ex2(__uint_as_float(vhi));
                }
            }
        };
        auto ldcc = [&](int it, int h, uint64_t (&cc)[2]) {
            const float* ct = gcb + it * NT + h * 16;
            float2 f0 = __ldg(reinterpret_cast<const float2*>(ct));
            float2 f1 = __ldg(reinterpret_cast<const float2*>(ct + 8));
            cc[0] = pk2(f0.x, f0.y);
            cc[1] = pk2(f1.x, f1.y);
        };

        mbar_wait(fullA[0], 0);
        ldcc(0, 0, pcc0);
        ldcc(0, 1, pcc1);
        burst(Sb, 0, accA);
        burst(Sb, 1, accB);
        if (lane == 0) mbar_arrive(emptyA[0]);

        for (int it = 1; it < NTILES; it++) {
            const int st = it & 1, r = it >> 1;
            mbar_wait(fullA[st], r & 1);
            const uint32_t stb = Sb + (uint32_t)st * STAGE;
            uint64_t ncc0[2], ncc1[2];
            ldcc(it, 0, ncc0);
            ldcc(it, 1, ncc1);
            epi(accA, pcc0);
            burst(stb, 0, accA);
            epi(accB, pcc1);
            burst(stb, 1, accB);
            pcc0[0] = ncc0[0]; pcc0[1] = ncc0[1];
            pcc1[0] = ncc1[0]; pcc1[1] = ncc1[1];
            if (lane == 0) mbar_arrive(emptyA[st]);
        }
        epi(accA, pcc0);
        epi(accB, pcc1);

        #pragma unroll
        for (int r = 0; r < 4; r++) {
            float sv = sums[r];
            sv += __shfl_xor_sync(0xffffffffu, sv, 1);
            sv += __shfl_xor_sync(0xffffffffu, sv, 2);
            if (c == 0) {
                int rl = wm * 32 + (r >> 1) * 16 + (r & 1) * 8 + g;
                red[wn][rl] = sv;
            }
        }
    }

    __syncthreads();
    if (tid < MT) {
        float tot = red[0][tid] + red[1][tid] + red[2][tid] + red[3][tid];
        g_part[split * MM + m0 + tid] = tot;
    }
    __syncthreads();

    if (tid == 0) {
        __threadfence();
        int old = atomicAdd(&g_cnt[blockIdx.x], 1);
        sdone_flag = (old == NSPLIT - 1) ? 1 : 0;
        if (sdone_flag) __threadfence();
    }
    __syncthreads();
    if (sdone_flag) {
        if (tid < MT) {
            float tot = 0.f;
            #pragma unroll
            for (int s = 0; s < NSPLIT; s++) tot += __ldcg(&g_part[s * MM + m0 + tid]);
            // coeff = -ln(50000) - 32*ln(2*pi); row term applied here
            out[m0 + tid] = -69.63184443f
                          + (log2f(tot) - g_RT[m0 + tid]) * 0.6931471805599453f;
        }
        __syncthreads();
        if (tid == 0) g_cnt[blockIdx.x] = 0;
    }
}

extern "C" void kernel_launch(void* const* d_in, const int* in_sizes, int n_in,
                              void* d_out, int out_size) {
    const float* x  = (const float*)d_in[0];   // [4096, 64]
    const float* X  = (const float*)d_in[1];   // [50000, 64]
    const float* bw = (const float*)d_in[2];   // [1]

    prep_all<<<NPAD / 32 + MM / 32, 256>>>(x, X, bw);   // 1696 blocks

    dim3 grid(MM / MT, NSPLIT);                         // (64, 23)
    kde_main2<<<grid, 288>>>(bw, (float*)d_out);
}

// round 11
// speedup vs baseline: 1.0871x; 1.0871x over previous
#include <cuda_runtime.h>
#include <cuda_bf16.h>
#include <cstdint>

// GaussianKernelDensity: out[m] = coeff + logsumexp_n( -||x_m - X_n||^2 / (2 b^2) )
// M=4096, N=50000, D=64.  (tcgen05 unavailable: harness targets plain sm_100)
//  Launch 1: prep_all — pack x,X to bf16; colc = -|X|^2*s, rowt = +|x|^2*s.
//  Launch 2: kde_main — 9 warps/CTA. Warp 8: cp.async producer filling a
//            2-stage ring of {B tile (SW128) + 128 column constants}.
//            Warps 0-7: software-pipelined consumers with double-buffered
//            accumulators P/Q — each epilogue consumes a burst issued one
//            burst earlier (drained), column constants read from the ring
//            stage via LDS (zero resident registers), row term applied at
//            the final log2. Empty-arrive for a stage happens only after
//            the epilogues that read its constants.

#define MM 4096
#define NN 50000
#define DD 64
#define NPAD 50176
#define NSPLIT 23
#define CHUNK 2176              // 17 * 128
#define NTILES 17
#define MT 64
#define NT 128
#define BSZ 16384               // B tile bytes (128 rows * 128 B)
#define CTOFF 16384             // ctile offset within a stage
#define SSZ 16896               // stage stride: B tile + 512B ctile

// device scratch
__device__ __nv_bfloat16 g_Xb[NPAD * DD];
__device__ float         g_CT[NPAD];       // -|X_n|^2 * s  (pad rows: -1000)
__device__ __nv_bfloat16 g_xb[MM * DD];
__device__ float         g_RT[MM];         // +|x_m|^2 * s  (subtracted at end)
__device__ float         g_part[NSPLIT * MM];
__device__ int           g_cnt[MM / MT];

#define LDSM4(r0, r1, r2, r3, addr)                                              \
    asm volatile("ldmatrix.sync.aligned.m8n8.x4.shared.b16 {%0,%1,%2,%3}, [%4];" \
                 : "=r"(r0), "=r"(r1), "=r"(r2), "=r"(r3) : "r"(addr))

__device__ __forceinline__ void cp16(uint32_t dst, const void* src) {
    asm volatile("cp.async.cg.shared.global [%0], [%1], 16;" :: "r"(dst), "l"(src));
}
__device__ __forceinline__ uint32_t smem_u32(const void* p) {
    return (uint32_t)__cvta_generic_to_shared(p);
}
__device__ __forceinline__ void mbar_init(uint32_t a, uint32_t cnt) {
    asm volatile("mbarrier.init.shared.b64 [%0], %1;" :: "r"(a), "r"(cnt) : "memory");
}
__device__ __forceinline__ void mbar_arrive(uint32_t a) {
    asm volatile("mbarrier.arrive.shared.b64 _, [%0];" :: "r"(a) : "memory");
}
__device__ __forceinline__ void cp_async_mbar_arrive(uint32_t a) {
    asm volatile("cp.async.mbarrier.arrive.noinc.shared.b64 [%0];" :: "r"(a) : "memory");
}
__device__ __forceinline__ void mbar_wait(uint32_t a, uint32_t parity) {
    asm volatile(
        "{\n\t.reg .pred P;\n\t"
        "WL_%=:\n\t"
        "mbarrier.try_wait.parity.shared.b64 P, [%0], %1;\n\t"
        "@!P bra WL_%=;\n\t"
        "}" :: "r"(a), "r"(parity) : "memory");
}
__device__ __forceinline__ float ex2(float x) {
    float r;
    asm("ex2.approx.ftz.f32 %0, %1;" : "=f"(r) : "f"(x));
    return r;
}

// ---- packed f32x2 helpers (Blackwell) ----
__device__ __forceinline__ uint64_t pk2(float lo, float hi) {
    uint64_t r;
    asm("mov.b64 %0, {%1, %2};" : "=l"(r) : "f"(lo), "f"(hi));
    return r;
}
__device__ __forceinline__ void upk2(uint32_t& lo, uint32_t& hi, uint64_t v) {
    asm("mov.b64 {%0, %1}, %2;" : "=r"(lo), "=r"(hi) : "l"(v));
}
__device__ __forceinline__ uint64_t fma2(uint64_t a, uint64_t b, uint64_t c) {
    uint64_t d;
    asm("fma.rn.f32x2 %0, %1, %2, %3;" : "=l"(d) : "l"(a), "l"(b), "l"(c));
    return d;
}

// ---------------- prep: pack + fold constants ----------------
__global__ void prep_all(const float* __restrict__ xin,
                         const float* __restrict__ Xin,
                         const float* __restrict__ bw) {
    const float b = bw[0];
    const float inv2 = 1.4426950408889634f / (2.f * b * b);   // log2e / (2 b^2)
    const int blk = blockIdx.x, tid = threadIdx.x;
    const int l8 = tid & 7;

    if (blk < NPAD / 32) {                       // X rows (incl. pad)
        int row = blk * 32 + (tid >> 3);
        uint4 packed = make_uint4(0u, 0u, 0u, 0u);
        __nv_bfloat16* hp = reinterpret_cast<__nv_bfloat16*>(&packed);
        float ss = 0.f;
        if (row < NN) {
            const float4* s4 = reinterpret_cast<const float4*>(Xin + row * DD + l8 * 8);
            float4 a = s4[0], d = s4[1];
            ss = a.x*a.x + a.y*a.y + a.z*a.z + a.w*a.w
               + d.x*d.x + d.y*d.y + d.z*d.z + d.w*d.w;
            hp[0] = __float2bfloat16_rn(a.x); hp[1] = __float2bfloat16_rn(a.y);
            hp[2] = __float2bfloat16_rn(a.z); hp[3] = __float2bfloat16_rn(a.w);
            hp[4] = __float2bfloat16_rn(d.x); hp[5] = __float2bfloat16_rn(d.y);
            hp[6] = __float2bfloat16_rn(d.z); hp[7] = __float2bfloat16_rn(d.w);
        }
        *reinterpret_cast<uint4*>(&g_Xb[row * DD + l8 * 8]) = packed;
        ss += __shfl_xor_sync(0xffffffffu, ss, 1);
        ss += __shfl_xor_sync(0xffffffffu, ss, 2);
        ss += __shfl_xor_sync(0xffffffffu, ss, 4);
        if (l8 == 0) g_CT[row] = (row < NN) ? (-ss * inv2) : -1000.f;
    } else {                                     // x rows
        int row = (blk - NPAD / 32) * 32 + (tid >> 3);
        const float4* s4 = reinterpret_cast<const float4*>(xin + row * DD + l8 * 8);
        float4 a = s4[0], d = s4[1];
        float ss = a.x*a.x + a.y*a.y + a.z*a.z + a.w*a.w
                 + d.x*d.x + d.y*d.y + d.z*d.z + d.w*d.w;
        uint4 packed;
        __nv_bfloat16* hp = reinterpret_cast<__nv_bfloat16*>(&packed);
        hp[0] = __float2bfloat16_rn(a.x); hp[1] = __float2bfloat16_rn(a.y);
        hp[2] = __float2bfloat16_rn(a.z); hp[3] = __float2bfloat16_rn(a.w);
        hp[4] = __float2bfloat16_rn(d.x); hp[5] = __float2bfloat16_rn(d.y);
        hp[6] = __float2bfloat16_rn(d.z); hp[7] = __float2bfloat16_rn(d.w);
        *reinterpret_cast<uint4*>(&g_xb[row * DD + l8 * 8]) = packed;
        ss += __shfl_xor_sync(0xffffffffu, ss, 1);
        ss += __shfl_xor_sync(0xffffffffu, ss, 2);
        ss += __shfl_xor_sync(0xffffffffu, ss, 4);
        if (l8 == 0) g_RT[row] = ss * inv2;      // positive; subtracted at end
    }
}

// ---------------- main: pipelined GEMM + MUFU exp2 sum ----------------
__global__ __launch_bounds__(288, 2) void kde_main(const float* __restrict__ bw,
                                                   float* __restrict__ out) {
    __shared__ __align__(1024) char S[2 * SSZ];              // B ring + ctiles
    __shared__ __align__(1024) char XS[MT * 128];            // x tile (swizzled)
    __shared__ __align__(8) uint64_t mbars[4];               // full0,full1,empty0,empty1
    __shared__ float red[4][MT];
    __shared__ int sdone_flag;

    const int tid  = threadIdx.x;
    const int warp = tid >> 5;
    const int lane = tid & 31;

    const int m0    = blockIdx.x * MT;
    const int split = blockIdx.y;
    const int n0    = split * CHUNK;

    const uint32_t Sb = smem_u32(S);
    const uint32_t fullA[2]  = { smem_u32(&mbars[0]), smem_u32(&mbars[1]) };
    const uint32_t emptyA[2] = { smem_u32(&mbars[2]), smem_u32(&mbars[3]) };

    if (tid == 0) {
        mbar_init(fullA[0], 32); mbar_init(fullA[1], 32);
        mbar_init(emptyA[0], 8); mbar_init(emptyA[1], 8);
    }

    // consumers stage the x tile, swizzled
    if (warp < 8) {
        int row = tid >> 2, q = tid & 3;
        const uint4* s = reinterpret_cast<const uint4*>(g_xb + (m0 + row) * DD + q * 16);
        uint4 v0 = s[0], v1 = s[1];
        int base = row * 128;
        int msk = row & 7;
        *reinterpret_cast<uint4*>(XS + base + (((2 * q)     ^ msk) * 16)) = v0;
        *reinterpret_cast<uint4*>(XS + base + (((2 * q + 1) ^ msk) * 16)) = v1;
    }
    __syncthreads();   // mbarriers initialized + x tile visible

    if (warp == 8) {
        // ================= producer warp =================
        const int r0 = lane >> 3, ch = lane & 7;
        const __nv_bfloat16* src = g_Xb + (n0 + r0) * DD + ch * 8;
        const float* csrc = g_CT + n0 + lane * 4;
        const uint32_t de  = (uint32_t)(r0 * 128 + ((ch ^ r0) * 16));
        const uint32_t dof = (uint32_t)(r0 * 128 + 512 + ((ch ^ r0 ^ 4) * 16));
        for (int it = 0; it < NTILES; it++) {
            const int st = it & 1;
            if (it >= 2) mbar_wait(emptyA[st], ((it - 2) >> 1) & 1);
            const uint32_t base = Sb + (uint32_t)st * SSZ;
            #pragma unroll
            for (int q = 0; q < 32; q += 2) {
                cp16(base + q * 512 + de,  src);  src += 4 * DD;
                cp16(base + q * 512 + dof, src);  src += 4 * DD;
            }
            cp16(base + CTOFF + lane * 16, csrc + it * NT);
            cp_async_mbar_arrive(fullA[st]);
        }
    } else {
        // ================= consumer warps =================
        const int g = lane >> 2;
        const int c = lane & 3;
        const int wm = warp >> 2;     // 0..1 (M)
        const int wn = warp & 3;      // 0..3 (N)

        const float b    = bw[0];
        const float inv4 = 1.4426950408889634f / (b * b);   // log2e / b^2
        const uint64_t inv42 = pk2(inv4, inv4);

        // A fragments for the whole lifetime
        const int lr = (lane & 7) + ((lane >> 3) & 1) * 8;
        const int cb = lane >> 4;
        uint32_t afr[4][8];
        #pragma unroll
        for (int i = 0; i < 2; i++) {
            int rowp = wm * 32 + i * 16 + lr;
            uint32_t rb = smem_u32(XS) + rowp * 128;
            int rm = rowp & 7;
            #pragma unroll
            for (int ks = 0; ks < 4; ks++) {
                uint32_t a0, a1, a2, a3;
                LDSM4(a0, a1, a2, a3, rb + (((ks * 2 + cb) ^ rm) * 16));
                afr[ks][i * 4 + 0] = a0; afr[ks][i * 4 + 1] = a1;
                afr[ks][i * 4 + 2] = a2; afr[ks][i * 4 + 3] = a3;
            }
        }

        uint32_t rB_off[2]; int rB_msk[2];
        #pragma unroll
        for (int h = 0; h < 2; h++) {
            int rowp = wn * 32 + h * 16 + lr;
            rB_off[h] = (uint32_t)(rowp * 128);
            rB_msk[h] = rowp & 7;
        }

        // ctile byte offset for this thread (within a stage): + h*64 + jn*32
        const int ccoff = CTOFF + (wn * 32 + 2 * c) * 4;

        float P[2][2][4], Q[2][2][4];
        float sums[4] = {0.f, 0.f, 0.f, 0.f};

        auto burst = [&](uint32_t stb, int h, float (&acc)[2][2][4]) {
            #pragma unroll
            for (int i = 0; i < 2; i++)
                #pragma unroll
                for (int jn = 0; jn < 2; jn++)
                    #pragma unroll
                    for (int q = 0; q < 4; q++) acc[i][jn][q] = 0.f;
            #pragma unroll
            for (int ks = 0; ks < 4; ks++) {
                uint32_t b0, b1, b2, b3;
                uint32_t addr = stb + rB_off[h] + (((ks * 2 + cb) ^ rB_msk[h]) * 16);
                LDSM4(b0, b1, b2, b3, addr);
                #pragma unroll
                for (int i = 0; i < 2; i++) {
                    asm volatile(
                        "mma.sync.aligned.m16n8k16.row.col.f32.bf16.bf16.f32 "
                        "{%0,%1,%2,%3}, {%4,%5,%6,%7}, {%8,%9}, {%0,%1,%2,%3};"
                        : "+f"(acc[i][0][0]), "+f"(acc[i][0][1]),
                          "+f"(acc[i][0][2]), "+f"(acc[i][0][3])
                        : "r"(afr[ks][i * 4 + 0]), "r"(afr[ks][i * 4 + 1]),
                          "r"(afr[ks][i * 4 + 2]), "r"(afr[ks][i * 4 + 3]),
                          "r"(b0), "r"(b2));
                    asm volatile(
                        "mma.sync.aligned.m16n8k16.row.col.f32.bf16.bf16.f32 "
                        "{%0,%1,%2,%3}, {%4,%5,%6,%7}, {%8,%9}, {%0,%1,%2,%3};"
                        : "+f"(acc[i][1][0]), "+f"(acc[i][1][1]),
                          "+f"(acc[i][1][2]), "+f"(acc[i][1][3])
                        : "r"(afr[ks][i * 4 + 0]), "r"(afr[ks][i * 4 + 1]),
                          "r"(afr[ks][i * 4 + 2]), "r"(afr[ks][i * 4 + 3]),
                          "r"(b1), "r"(b3));
                }
            }
        };
        // epi: cc read from the ring stage (ccbase = stage base of the tile
        // the acc belongs to); e = ex2(acc*s + cc) summed per row.
        auto epi = [&](float (&acc)[2][2][4], const char* ccb, int h) {
            float2 c0 = *reinterpret_cast<const float2*>(ccb + ccoff + h * 64);
            float2 c1 = *reinterpret_cast<const float2*>(ccb + ccoff + h * 64 + 32);
            uint64_t cc0 = pk2(c0.x, c0.y);
            uint64_t cc1 = pk2(c1.x, c1.y);
            #pragma unroll
            for (int r = 0; r < 4; r++) {
                const int i = r >> 1, hf = r & 1;
                uint64_t v0 = fma2(pk2(acc[i][0][hf * 2], acc[i][0][hf * 2 + 1]),
                                   inv42, cc0);
                uint64_t v1 = fma2(pk2(acc[i][1][hf * 2], acc[i][1][hf * 2 + 1]),
                                   inv42, cc1);
                uint32_t a, d;
                upk2(a, d, v0);
                sums[r] += ex2(__uint_as_float(a));
                sums[r] += ex2(__uint_as_float(d));
                upk2(a, d, v1);
                sums[r] += ex2(__uint_as_float(a));
                sums[r] += ex2(__uint_as_float(d));
            }
        };

        // ---- prologue: tile 0 fills both acc buffers; no empty-arrive yet
        // (stage 0's ctile is read by the epis in iteration 1).
        mbar_wait(fullA[0], 0);
        burst(Sb, 0, P);
        burst(Sb, 1, Q);

        // ---- pipelined main loop ----
        for (int it = 1; it < NTILES; it++) {
            const int st = it & 1, r = it >> 1;
            mbar_wait(fullA[st], r & 1);
            const uint32_t stb = Sb + (uint32_t)st * SSZ;
            const char* ccb = S + (st ^ 1) * SSZ;   // stage of tile it-1
            epi(P, ccb, 0);          // tile it-1 h0 (drained long ago)
            burst(stb, 0, P);        // tile it h0
            epi(Q, ccb, 1);          // tile it-1 h1
            burst(stb, 1, Q);        // tile it h1
            if (lane == 0) mbar_arrive(emptyA[st ^ 1]);   // old stage fully read
        }
        // ---- tail: tile NTILES-1 lives in stage (NTILES-1)&1 = 0
        {
            const char* ccb = S + ((NTILES - 1) & 1) * SSZ;
            epi(P, ccb, 0);
            epi(Q, ccb, 1);
        }

        // quad reduce, store to red[]
        #pragma unroll
        for (int r = 0; r < 4; r++) {
            float sv = sums[r];
            sv += __shfl_xor_sync(0xffffffffu, sv, 1);
            sv += __shfl_xor_sync(0xffffffffu, sv, 2);
            if (c == 0) {
                int rl = wm * 32 + (r >> 1) * 16 + (r & 1) * 8 + g;
                red[wn][rl] = sv;
            }
        }
    }

    __syncthreads();
    if (tid < MT) {
        float tot = red[0][tid] + red[1][tid] + red[2][tid] + red[3][tid];
        g_part[split * MM + m0 + tid] = tot;
    }
    __syncthreads();

    // ---- tail CTA per m-block merges the 23 split sums ----
    if (tid == 0) {
        __threadfence();
        int old = atomicAdd(&g_cnt[blockIdx.x], 1);
        sdone_flag = (old == NSPLIT - 1) ? 1 : 0;
        if (sdone_flag) __threadfence();
    }
    __syncthreads();
    if (sdone_flag) {
        if (tid < MT) {
            float tot = 0.f;
            #pragma unroll
            for (int s = 0; s < NSPLIT; s++) tot += __ldcg(&g_part[s * MM + m0 + tid]);
            // coeff = -ln(50000) - 32*ln(2*pi); row term applied here
            out[m0 + tid] = -69.63184443f
                          + (log2f(tot) - g_RT[m0 + tid]) * 0.6931471805599453f;
        }
        __syncthreads();
        if (tid == 0) g_cnt[blockIdx.x] = 0;   // reset for next graph replay
    }
}

extern "C" void kernel_launch(void* const* d_in, const int* in_sizes, int n_in,
                              void* d_out, int out_size) {
    const float* x  = (const float*)d_in[0];   // [4096, 64]
    const float* X  = (const float*)d_in[1];   // [50000, 64]
    const float* bw = (const float*)d_in[2];   // [1]

    prep_all<<<NPAD / 32 + MM / 32, 256>>>(x, X, bw);   // 1696 blocks

    dim3 grid(MM / MT, NSPLIT);                         // (64, 23)
    kde_main<<<grid, 288>>>(bw, (float*)d_out);
}

// round 12
// speedup vs baseline: 1.1396x; 1.0483x over previous
#include <cuda_runtime.h>
#include <cuda_bf16.h>
#include <cstdint>

// GaussianKernelDensity: out[m] = coeff + logsumexp_n( -||x_m - X_n||^2 / (2 b^2) )
// M=4096, N=50000, D=64.  (tcgen05 unavailable: harness targets plain sm_100)
//  Launch 1: prep_all — pack x,X to bf16; colc = -|X|^2*s, rowt = +|x|^2*s.
//  Launch 2: kde_main — 9 warps/CTA. Warp 8: cp.async producer, 2-stage SW128
//            B ring, full/empty mbarriers (empty-arrive right after the LDSMs
//            so the producer keeps its full 2-tile slack). Warps 0-7: both
//            halves' HMMA bursts issued back-to-back into double accumulators,
//            THEN both epilogues (MUFU ex2) — one-burst drain distance with no
//            extra cc registers. Row term folded out (applied at final log2).

#define MM 4096
#define NN 50000
#define DD 64
#define NPAD 50176
#define NSPLIT 23
#define CHUNK 2176              // 17 * 128
#define NTILES 17
#define MT 64
#define NT 128
#define STAGE 16384             // 128 rows * 128 B

// device scratch
__device__ __nv_bfloat16 g_Xb[NPAD * DD];
__device__ float         g_CT[NPAD];       // -|X_n|^2 * s  (pad rows: -1000)
__device__ __nv_bfloat16 g_xb[MM * DD];
__device__ float         g_RT[MM];         // +|x_m|^2 * s  (subtracted at end)
__device__ float         g_part[NSPLIT * MM];
__device__ int           g_cnt[MM / MT];

#define LDSM4(r0, r1, r2, r3, addr)                                              \
    asm volatile("ldmatrix.sync.aligned.m8n8.x4.shared.b16 {%0,%1,%2,%3}, [%4];" \
                 : "=r"(r0), "=r"(r1), "=r"(r2), "=r"(r3) : "r"(addr))

__device__ __forceinline__ void cp16(uint32_t dst, const void* src) {
    asm volatile("cp.async.cg.shared.global [%0], [%1], 16;" :: "r"(dst), "l"(src));
}
__device__ __forceinline__ uint32_t smem_u32(const void* p) {
    return (uint32_t)__cvta_generic_to_shared(p);
}
__device__ __forceinline__ void mbar_init(uint32_t a, uint32_t cnt) {
    asm volatile("mbarrier.init.shared.b64 [%0], %1;" :: "r"(a), "r"(cnt) : "memory");
}
__device__ __forceinline__ void mbar_arrive(uint32_t a) {
    asm volatile("mbarrier.arrive.shared.b64 _, [%0];" :: "r"(a) : "memory");
}
__device__ __forceinline__ void cp_async_mbar_arrive(uint32_t a) {
    asm volatile("cp.async.mbarrier.arrive.noinc.shared.b64 [%0];" :: "r"(a) : "memory");
}
__device__ __forceinline__ void mbar_wait(uint32_t a, uint32_t parity) {
    asm volatile(
        "{\n\t.reg .pred P;\n\t"
        "WL_%=:\n\t"
        "mbarrier.try_wait.parity.shared.b64 P, [%0], %1;\n\t"
        "@!P bra WL_%=;\n\t"
        "}" :: "r"(a), "r"(parity) : "memory");
}
__device__ __forceinline__ float ex2(float x) {
    float r;
    asm("ex2.approx.ftz.f32 %0, %1;" : "=f"(r) : "f"(x));
    return r;
}

// ---- packed f32x2 helpers (Blackwell) ----
__device__ __forceinline__ uint64_t pk2(float lo, float hi) {
    uint64_t r;
    asm("mov.b64 %0, {%1, %2};" : "=l"(r) : "f"(lo), "f"(hi));
    return r;
}
__device__ __forceinline__ void upk2(uint32_t& lo, uint32_t& hi, uint64_t v) {
    asm("mov.b64 {%0, %1}, %2;" : "=r"(lo), "=r"(hi) : "l"(v));
}
__device__ __forceinline__ uint64_t fma2(uint64_t a, uint64_t b, uint64_t c) {
    uint64_t d;
    asm("fma.rn.f32x2 %0, %1, %2, %3;" : "=l"(d) : "l"(a), "l"(b), "l"(c));
    return d;
}

// ---------------- prep: pack + fold constants ----------------
__global__ void prep_all(const float* __restrict__ xin,
                         const float* __restrict__ Xin,
                         const float* __restrict__ bw) {
    const float b = bw[0];
    const float inv2 = 1.4426950408889634f / (2.f * b * b);   // log2e / (2 b^2)
    const int blk = blockIdx.x, tid = threadIdx.x;
    const int l8 = tid & 7;

    if (blk < NPAD / 32) {                       // X rows (incl. pad)
        int row = blk * 32 + (tid >> 3);
        uint4 packed = make_uint4(0u, 0u, 0u, 0u);
        __nv_bfloat16* hp = reinterpret_cast<__nv_bfloat16*>(&packed);
        float ss = 0.f;
        if (row < NN) {
            const float4* s4 = reinterpret_cast<const float4*>(Xin + row * DD + l8 * 8);
            float4 a = s4[0], d = s4[1];
            ss = a.x*a.x + a.y*a.y + a.z*a.z + a.w*a.w
               + d.x*d.x + d.y*d.y + d.z*d.z + d.w*d.w;
            hp[0] = __float2bfloat16_rn(a.x); hp[1] = __float2bfloat16_rn(a.y);
            hp[2] = __float2bfloat16_rn(a.z); hp[3] = __float2bfloat16_rn(a.w);
            hp[4] = __float2bfloat16_rn(d.x); hp[5] = __float2bfloat16_rn(d.y);
            hp[6] = __float2bfloat16_rn(d.z); hp[7] = __float2bfloat16_rn(d.w);
        }
        *reinterpret_cast<uint4*>(&g_Xb[row * DD + l8 * 8]) = packed;
        ss += __shfl_xor_sync(0xffffffffu, ss, 1);
        ss += __shfl_xor_sync(0xffffffffu, ss, 2);
        ss += __shfl_xor_sync(0xffffffffu, ss, 4);
        if (l8 == 0) g_CT[row] = (row < NN) ? (-ss * inv2) : -1000.f;
    } else {                                     // x rows
        int row = (blk - NPAD / 32) * 32 + (tid >> 3);
        const float4* s4 = reinterpret_cast<const float4*>(xin + row * DD + l8 * 8);
        float4 a = s4[0], d = s4[1];
        float ss = a.x*a.x + a.y*a.y + a.z*a.z + a.w*a.w
                 + d.x*d.x + d.y*d.y + d.z*d.z + d.w*d.w;
        uint4 packed;
        __nv_bfloat16* hp = reinterpret_cast<__nv_bfloat16*>(&packed);
        hp[0] = __float2bfloat16_rn(a.x); hp[1] = __float2bfloat16_rn(a.y);
        hp[2] = __float2bfloat16_rn(a.z); hp[3] = __float2bfloat16_rn(a.w);
        hp[4] = __float2bfloat16_rn(d.x); hp[5] = __float2bfloat16_rn(d.y);
        hp[6] = __float2bfloat16_rn(d.z); hp[7] = __float2bfloat16_rn(d.w);
        *reinterpret_cast<uint4*>(&g_xb[row * DD + l8 * 8]) = packed;
        ss += __shfl_xor_sync(0xffffffffu, ss, 1);
        ss += __shfl_xor_sync(0xffffffffu, ss, 2);
        ss += __shfl_xor_sync(0xffffffffu, ss, 4);
        if (l8 == 0) g_RT[row] = ss * inv2;      // positive; subtracted at end
    }
}

// ---------------- main: producer/consumer GEMM + MUFU exp2 sum ----------------
__global__ __launch_bounds__(288, 2) void kde_main(const float* __restrict__ bw,
                                                   float* __restrict__ out) {
    __shared__ __align__(1024) char S[2 * STAGE];            // 32KB B ring
    __shared__ __align__(1024) char XS[MT * 128];            //  8KB x tile (swizzled)
    __shared__ __align__(8) uint64_t mbars[4];               // full0,full1,empty0,empty1
    __shared__ float red[4][MT];
    __shared__ int sdone_flag;

    const int tid  = threadIdx.x;
    const int warp = tid >> 5;
    const int lane = tid & 31;

    const int m0    = blockIdx.x * MT;
    const int split = blockIdx.y;
    const int n0    = split * CHUNK;

    const uint32_t Sb = smem_u32(S);
    const uint32_t fullA[2]  = { smem_u32(&mbars[0]), smem_u32(&mbars[1]) };
    const uint32_t emptyA[2] = { smem_u32(&mbars[2]), smem_u32(&mbars[3]) };

    if (tid == 0) {
        mbar_init(fullA[0], 32); mbar_init(fullA[1], 32);
        mbar_init(emptyA[0], 8); mbar_init(emptyA[1], 8);
    }

    // consumers (256 threads) stage the x tile, swizzled
    if (warp < 8) {
        int row = tid >> 2, q = tid & 3;
        const uint4* s = reinterpret_cast<const uint4*>(g_xb + (m0 + row) * DD + q * 16);
        uint4 v0 = s[0], v1 = s[1];
        int base = row * 128;
        int msk = row & 7;
        *reinterpret_cast<uint4*>(XS + base + (((2 * q)     ^ msk) * 16)) = v0;
        *reinterpret_cast<uint4*>(XS + base + (((2 * q + 1) ^ msk) * 16)) = v1;
    }
    __syncthreads();   // mbarriers initialized + x tile visible

    if (warp == 8) {
        // ================= producer warp =================
        const int r0 = lane >> 3, ch = lane & 7;
        const __nv_bfloat16* src = g_Xb + (n0 + r0) * DD + ch * 8;
        const uint32_t de  = (uint32_t)(r0 * 128 + ((ch ^ r0) * 16));
        const uint32_t dof = (uint32_t)(r0 * 128 + 512 + ((ch ^ r0 ^ 4) * 16));
        for (int it = 0; it < NTILES; it++) {
            const int st = it & 1;
            if (it >= 2) mbar_wait(emptyA[st], ((it - 2) >> 1) & 1);
            const uint32_t base = Sb + (uint32_t)st * STAGE;
            #pragma unroll
            for (int q = 0; q < 32; q += 2) {
                cp16(base + q * 512 + de,  src);  src += 4 * DD;
                cp16(base + q * 512 + dof, src);  src += 4 * DD;
            }
            cp_async_mbar_arrive(fullA[st]);
        }
    } else {
        // ================= consumer warps =================
        const int g = lane >> 2;
        const int c = lane & 3;
        const int wm = warp >> 2;     // 0..1 (M)
        const int wn = warp & 3;      // 0..3 (N)

        const float b    = bw[0];
        const float inv4 = 1.4426950408889634f / (b * b);   // log2e / b^2
        const uint64_t inv42 = pk2(inv4, inv4);

        // A fragments for the whole lifetime
        const int lr = (lane & 7) + ((lane >> 3) & 1) * 8;
        const int cb = lane >> 4;
        uint32_t afr[4][8];
        #pragma unroll
        for (int i = 0; i < 2; i++) {
            int rowp = wm * 32 + i * 16 + lr;
            uint32_t rb = smem_u32(XS) + rowp * 128;
            int rm = rowp & 7;
            #pragma unroll
            for (int ks = 0; ks < 4; ks++) {
                uint32_t a0, a1, a2, a3;
                LDSM4(a0, a1, a2, a3, rb + (((ks * 2 + cb) ^ rm) * 16));
                afr[ks][i * 4 + 0] = a0; afr[ks][i * 4 + 1] = a1;
                afr[ks][i * 4 + 2] = a2; afr[ks][i * 4 + 3] = a3;
            }
        }

        uint32_t rB_off[2]; int rB_msk[2];
        #pragma unroll
        for (int h = 0; h < 2; h++) {
            int rowp = wn * 32 + h * 16 + lr;
            rB_off[h] = (uint32_t)(rowp * 128);
            rB_msk[h] = rowp & 7;
        }

        const float* gc = g_CT + n0 + wn * 32 + 2 * c;
        float2 cv[4];
        #pragma unroll
        for (int j = 0; j < 4; j++) cv[j] = __ldg((const float2*)(gc + j * 8));

        float accA[2][2][4], accB[2][2][4];
        float sums[4] = {0.f, 0.f, 0.f, 0.f};

        auto burst = [&](uint32_t stb, int h, float (&acc)[2][2][4]) {
            #pragma unroll
            for (int i = 0; i < 2; i++)
                #pragma unroll
                for (int jn = 0; jn < 2; jn++)
                    #pragma unroll
                    for (int q = 0; q < 4; q++) acc[i][jn][q] = 0.f;
            #pragma unroll
            for (int ks = 0; ks < 4; ks++) {
                uint32_t b0, b1, b2, b3;
                uint32_t addr = stb + rB_off[h] + (((ks * 2 + cb) ^ rB_msk[h]) * 16);
                LDSM4(b0, b1, b2, b3, addr);
                #pragma unroll
                for (int i = 0; i < 2; i++) {
                    asm volatile(
                        "mma.sync.aligned.m16n8k16.row.col.f32.bf16.bf16.f32 "
                        "{%0,%1,%2,%3}, {%4,%5,%6,%7}, {%8,%9}, {%0,%1,%2,%3};"
                        : "+f"(acc[i][0][0]), "+f"(acc[i][0][1]),
                          "+f"(acc[i][0][2]), "+f"(acc[i][0][3])
                        : "r"(afr[ks][i * 4 + 0]), "r"(afr[ks][i * 4 + 1]),
                          "r"(afr[ks][i * 4 + 2]), "r"(afr[ks][i * 4 + 3]),
                          "r"(b0), "r"(b2));
                    asm volatile(
                        "mma.sync.aligned.m16n8k16.row.col.f32.bf16.bf16.f32 "
                        "{%0,%1,%2,%3}, {%4,%5,%6,%7}, {%8,%9}, {%0,%1,%2,%3};"
                        : "+f"(acc[i][1][0]), "+f"(acc[i][1][1]),
                          "+f"(acc[i][1][2]), "+f"(acc[i][1][3])
                        : "r"(afr[ks][i * 4 + 0]), "r"(afr[ks][i * 4 + 1]),
                          "r"(afr[ks][i * 4 + 2]), "r"(afr[ks][i * 4 + 3]),
                          "r"(b1), "r"(b3));
                }
            }
        };
        // epi: e = ex2(acc*s + cc); cc passed as the half's two packed pairs.
        auto epi = [&](float (&acc)[2][2][4], uint64_t cc0, uint64_t cc1) {
            #pragma unroll
            for (int r = 0; r < 4; r++) {
                const int i = r >> 1, hf = r & 1;
                uint64_t v0 = fma2(pk2(acc[i][0][hf * 2], acc[i][0][hf * 2 + 1]),
                                   inv42, cc0);
                uint64_t v1 = fma2(pk2(acc[i][1][hf * 2], acc[i][1][hf * 2 + 1]),
                                   inv42, cc1);
                uint32_t a, d;
                upk2(a, d, v0);
                sums[r] += ex2(__uint_as_float(a));
                sums[r] += ex2(__uint_as_float(d));
                upk2(a, d, v1);
                sums[r] += ex2(__uint_as_float(a));
                sums[r] += ex2(__uint_as_float(d));
            }
        };

        for (int it = 0; it < NTILES; it++) {
            const int st = it & 1, r = it >> 1;
            const uint32_t stb = Sb + (uint32_t)st * STAGE;
            mbar_wait(fullA[st], r & 1);

            uint64_t cc0 = pk2(cv[0].x, cv[0].y);
            uint64_t cc1 = pk2(cv[1].x, cv[1].y);
            uint64_t cc2 = pk2(cv[2].x, cv[2].y);
            uint64_t cc3 = pk2(cv[3].x, cv[3].y);
            const int pf = (it + 1 < NTILES) ? it + 1 : it;
            #pragma unroll
            for (int j = 0; j < 4; j++)
                cv[j] = __ldg((const float2*)(gc + pf * NT + j * 8));

            burst(stb, 0, accA);            // h0 -> accA
            burst(stb, 1, accB);            // h1 -> accB
            if (lane == 0) mbar_arrive(emptyA[st]);   // all LDSMs done; stage free

            epi(accA, cc0, cc1);            // one-burst drain distance
            epi(accB, cc2, cc3);
        }

        // quad reduce, store to red[]
        #pragma unroll
        for (int r = 0; r < 4; r++) {
            float sv = sums[r];
            sv += __shfl_xor_sync(0xffffffffu, sv, 1);
            sv += __shfl_xor_sync(0xffffffffu, sv, 2);
            if (c == 0) {
                int rl = wm * 32 + (r >> 1) * 16 + (r & 1) * 8 + g;
                red[wn][rl] = sv;
            }
        }
    }

    __syncthreads();
    if (tid < MT) {
        float tot = red[0][tid] + red[1][tid] + red[2][tid] + red[3][tid];
        g_part[split * MM + m0 + tid] = tot;
    }
    __syncthreads();

    // ---- tail CTA per m-block merges the 23 split sums ----
    if (tid == 0) {
        __threadfence();
        int old = atomicAdd(&g_cnt[blockIdx.x], 1);
        sdone_flag = (old == NSPLIT - 1) ? 1 : 0;
        if (sdone_flag) __threadfence();
    }
    __syncthreads();
    if (sdone_flag) {
        if (tid < MT) {
            float tot = 0.f;
            #pragma unroll
            for (int s = 0; s < NSPLIT; s++) tot += __ldcg(&g_part[s * MM + m0 + tid]);
            // coeff = -ln(50000) - 32*ln(2*pi); row term applied here
            out[m0 + tid] = -69.63184443f
                          + (log2f(tot) - g_RT[m0 + tid]) * 0.6931471805599453f;
        }
        __syncthreads();
        if (tid == 0) g_cnt[blockIdx.x] = 0;   // reset for next graph replay
    }
}

extern "C" void kernel_launch(void* const* d_in, const int* in_sizes, int n_in,
                              void* d_out, int out_size) {
    const float* x  = (const float*)d_in[0];   // [4096, 64]
    const float* X  = (const float*)d_in[1];   // [50000, 64]
    const float* bw = (const float*)d_in[2];   // [1]

    prep_all<<<NPAD / 32 + MM / 32, 256>>>(x, X, bw);   // 1696 blocks

    dim3 grid(MM / MT, NSPLIT);                         // (64, 23)
    kde_main<<<grid, 288>>>(bw, (float*)d_out);
}

// round 13
// speedup vs baseline: 1.1726x; 1.0290x over previous
#include <cuda_runtime.h>
#include <cuda_bf16.h>
#include <cstdint>

// GaussianKernelDensity: out[m] = coeff + logsumexp_n( -||x_m - X_n||^2 / (2 b^2) )
// M=4096, N=50000, D=64.  (tcgen05 unavailable: harness targets plain sm_100)
//  Launch 1: prep_all — pack x,X to bf16; colc = -|X|^2*s, rowt = +|x|^2*s.
//  Launch 2: kde_main — 17 warps/CTA, 2 CTA/SM (8.5 warps/SMSP for latency
//            hiding). Warp 16: cp.async producer, 2-stage SW128 B ring,
//            full/empty mbarriers. Warps 0-15: 4(M)x4(N) consumers, warp tile
//            16x32, double accumulators (both halves' HMMA bursts, then both
//            MUFU ex2 epilogues; cc via __ldg in the epilogue). Row term
//            folded out (applied at final log2). Reg cap 60 — no spills.

#define MM 4096
#define NN 50000
#define DD 64
#define NPAD 50176
#define NSPLIT 23
#define CHUNK 2176              // 17 * 128
#define NTILES 17
#define MT 64
#define NT 128
#define STAGE 16384             // 128 rows * 128 B

// device scratch
__device__ __nv_bfloat16 g_Xb[NPAD * DD];
__device__ float         g_CT[NPAD];       // -|X_n|^2 * s  (pad rows: -1000)
__device__ __nv_bfloat16 g_xb[MM * DD];
__device__ float         g_RT[MM];         // +|x_m|^2 * s  (subtracted at end)
__device__ float         g_part[NSPLIT * MM];
__device__ int           g_cnt[MM / MT];

#define LDSM4(r0, r1, r2, r3, addr)                                              \
    asm volatile("ldmatrix.sync.aligned.m8n8.x4.shared.b16 {%0,%1,%2,%3}, [%4];" \
                 : "=r"(r0), "=r"(r1), "=r"(r2), "=r"(r3) : "r"(addr))

__device__ __forceinline__ void cp16(uint32_t dst, const void* src) {
    asm volatile("cp.async.cg.shared.global [%0], [%1], 16;" :: "r"(dst), "l"(src));
}
__device__ __forceinline__ uint32_t smem_u32(const void* p) {
    return (uint32_t)__cvta_generic_to_shared(p);
}
__device__ __forceinline__ void mbar_init(uint32_t a, uint32_t cnt) {
    asm volatile("mbarrier.init.shared.b64 [%0], %1;" :: "r"(a), "r"(cnt) : "memory");
}
__device__ __forceinline__ void mbar_arrive(uint32_t a) {
    asm volatile("mbarrier.arrive.shared.b64 _, [%0];" :: "r"(a) : "memory");
}
__device__ __forceinline__ void cp_async_mbar_arrive(uint32_t a) {
    asm volatile("cp.async.mbarrier.arrive.noinc.shared.b64 [%0];" :: "r"(a) : "memory");
}
__device__ __forceinline__ void mbar_wait(uint32_t a, uint32_t parity) {
    asm volatile(
        "{\n\t.reg .pred P;\n\t"
        "WL_%=:\n\t"
        "mbarrier.try_wait.parity.shared.b64 P, [%0], %1;\n\t"
        "@!P bra WL_%=;\n\t"
        "}" :: "r"(a), "r"(parity) : "memory");
}
__device__ __forceinline__ float ex2(float x) {
    float r;
    asm("ex2.approx.ftz.f32 %0, %1;" : "=f"(r) : "f"(x));
    return r;
}

// ---- packed f32x2 helpers (Blackwell) ----
__device__ __forceinline__ uint64_t pk2(float lo, float hi) {
    uint64_t r;
    asm("mov.b64 %0, {%1, %2};" : "=l"(r) : "f"(lo), "f"(hi));
    return r;
}
__device__ __forceinline__ void upk2(uint32_t& lo, uint32_t& hi, uint64_t v) {
    asm("mov.b64 {%0, %1}, %2;" : "=r"(lo), "=r"(hi) : "l"(v));
}
__device__ __forceinline__ uint64_t fma2(uint64_t a, uint64_t b, uint64_t c) {
    uint64_t d;
    asm("fma.rn.f32x2 %0, %1, %2, %3;" : "=l"(d) : "l"(a), "l"(b), "l"(c));
    return d;
}

// ---------------- prep: pack + fold constants ----------------
__global__ void prep_all(const float* __restrict__ xin,
                         const float* __restrict__ Xin,
                         const float* __restrict__ bw) {
    const float b = bw[0];
    const float inv2 = 1.4426950408889634f / (2.f * b * b);   // log2e / (2 b^2)
    const int blk = blockIdx.x, tid = threadIdx.x;
    const int l8 = tid & 7;

    if (blk < NPAD / 32) {                       // X rows (incl. pad)
        int row = blk * 32 + (tid >> 3);
        uint4 packed = make_uint4(0u, 0u, 0u, 0u);
        __nv_bfloat16* hp = reinterpret_cast<__nv_bfloat16*>(&packed);
        float ss = 0.f;
        if (row < NN) {
            const float4* s4 = reinterpret_cast<const float4*>(Xin + row * DD + l8 * 8);
            float4 a = s4[0], d = s4[1];
            ss = a.x*a.x + a.y*a.y + a.z*a.z + a.w*a.w
               + d.x*d.x + d.y*d.y + d.z*d.z + d.w*d.w;
            hp[0] = __float2bfloat16_rn(a.x); hp[1] = __float2bfloat16_rn(a.y);
            hp[2] = __float2bfloat16_rn(a.z); hp[3] = __float2bfloat16_rn(a.w);
            hp[4] = __float2bfloat16_rn(d.x); hp[5] = __float2bfloat16_rn(d.y);
            hp[6] = __float2bfloat16_rn(d.z); hp[7] = __float2bfloat16_rn(d.w);
        }
        *reinterpret_cast<uint4*>(&g_Xb[row * DD + l8 * 8]) = packed;
        ss += __shfl_xor_sync(0xffffffffu, ss, 1);
        ss += __shfl_xor_sync(0xffffffffu, ss, 2);
        ss += __shfl_xor_sync(0xffffffffu, ss, 4);
        if (l8 == 0) g_CT[row] = (row < NN) ? (-ss * inv2) : -1000.f;
    } else {                                     // x rows
        int row = (blk - NPAD / 32) * 32 + (tid >> 3);
        const float4* s4 = reinterpret_cast<const float4*>(xin + row * DD + l8 * 8);
        float4 a = s4[0], d = s4[1];
        float ss = a.x*a.x + a.y*a.y + a.z*a.z + a.w*a.w
                 + d.x*d.x + d.y*d.y + d.z*d.z + d.w*d.w;
        uint4 packed;
        __nv_bfloat16* hp = reinterpret_cast<__nv_bfloat16*>(&packed);
        hp[0] = __float2bfloat16_rn(a.x); hp[1] = __float2bfloat16_rn(a.y);
        hp[2] = __float2bfloat16_rn(a.z); hp[3] = __float2bfloat16_rn(a.w);
        hp[4] = __float2bfloat16_rn(d.x); hp[5] = __float2bfloat16_rn(d.y);
        hp[6] = __float2bfloat16_rn(d.z); hp[7] = __float2bfloat16_rn(d.w);
        *reinterpret_cast<uint4*>(&g_xb[row * DD + l8 * 8]) = packed;
        ss += __shfl_xor_sync(0xffffffffu, ss, 1);
        ss += __shfl_xor_sync(0xffffffffu, ss, 2);
        ss += __shfl_xor_sync(0xffffffffu, ss, 4);
        if (l8 == 0) g_RT[row] = ss * inv2;      // positive; subtracted at end
    }
}

// ---------------- main: producer/consumer GEMM + MUFU exp2 sum ----------------
__global__ __launch_bounds__(544, 2) void kde_main(const float* __restrict__ bw,
                                                   float* __restrict__ out) {
    __shared__ __align__(1024) char S[2 * STAGE];            // 32KB B ring
    __shared__ __align__(1024) char XS[MT * 128];            //  8KB x tile (swizzled)
    __shared__ __align__(8) uint64_t mbars[4];               // full0,full1,empty0,empty1
    __shared__ float red[4][MT];
    __shared__ int sdone_flag;

    const int tid  = threadIdx.x;
    const int warp = tid >> 5;
    const int lane = tid & 31;

    const int m0    = blockIdx.x * MT;
    const int split = blockIdx.y;
    const int n0    = split * CHUNK;

    const uint32_t Sb = smem_u32(S);
    const uint32_t fullA[2]  = { smem_u32(&mbars[0]), smem_u32(&mbars[1]) };
    const uint32_t emptyA[2] = { smem_u32(&mbars[2]), smem_u32(&mbars[3]) };

    if (tid == 0) {
        mbar_init(fullA[0], 32); mbar_init(fullA[1], 32);
        mbar_init(emptyA[0], 16); mbar_init(emptyA[1], 16);
    }

    // first 256 threads stage the x tile, swizzled
    if (tid < 256) {
        int row = tid >> 2, q = tid & 3;
        const uint4* s = reinterpret_cast<const uint4*>(g_xb + (m0 + row) * DD + q * 16);
        uint4 v0 = s[0], v1 = s[1];
        int base = row * 128;
        int msk = row & 7;
        *reinterpret_cast<uint4*>(XS + base + (((2 * q)     ^ msk) * 16)) = v0;
        *reinterpret_cast<uint4*>(XS + base + (((2 * q + 1) ^ msk) * 16)) = v1;
    }
    __syncthreads();   // mbarriers initialized + x tile visible

    if (warp == 16) {
        // ================= producer warp =================
        const int r0 = lane >> 3, ch = lane & 7;
        const __nv_bfloat16* src = g_Xb + (n0 + r0) * DD + ch * 8;
        const uint32_t de  = (uint32_t)(r0 * 128 + ((ch ^ r0) * 16));
        const uint32_t dof = (uint32_t)(r0 * 128 + 512 + ((ch ^ r0 ^ 4) * 16));
        for (int it = 0; it < NTILES; it++) {
            const int st = it & 1;
            if (it >= 2) mbar_wait(emptyA[st], ((it - 2) >> 1) & 1);
            const uint32_t base = Sb + (uint32_t)st * STAGE;
            #pragma unroll
            for (int q = 0; q < 32; q += 2) {
                cp16(base + q * 512 + de,  src);  src += 4 * DD;
                cp16(base + q * 512 + dof, src);  src += 4 * DD;
            }
            cp_async_mbar_arrive(fullA[st]);
        }
    } else {
        // ================= consumer warps 0-15: 4(M) x 4(N), tile 16x32 ====
        const int g = lane >> 2;
        const int c = lane & 3;
        const int wm = warp >> 2;     // 0..3 (M: 16-row group)
        const int wn = warp & 3;      // 0..3 (N: 32-col group)

        const float b    = bw[0];
        const float inv4 = 1.4426950408889634f / (b * b);   // log2e / b^2
        const uint64_t inv42 = pk2(inv4, inv4);

        // A fragments for the whole lifetime: 16 rows, K=64 -> 4 LDSM.x4
        const int lr = (lane & 7) + ((lane >> 3) & 1) * 8;
        const int cb = lane >> 4;
        uint32_t afr[4][4];
        {
            int rowp = wm * 16 + lr;
            uint32_t rb = smem_u32(XS) + rowp * 128;
            int rm = rowp & 7;
            #pragma unroll
            for (int ks = 0; ks < 4; ks++)
                LDSM4(afr[ks][0], afr[ks][1], afr[ks][2], afr[ks][3],
                      rb + (((ks * 2 + cb) ^ rm) * 16));
        }

        uint32_t rB_off[2]; int rB_msk[2];
        #pragma unroll
        for (int h = 0; h < 2; h++) {
            int rowp = wn * 32 + h * 16 + lr;
            rB_off[h] = (uint32_t)(rowp * 128);
            rB_msk[h] = rowp & 7;
        }

        const float* gc = g_CT + n0 + wn * 32 + 2 * c;   // + h*16 + jn*8 + it*NT

        float accA[2][4], accB[2][4];      // [jn][q], one half each
        float sums[2] = {0.f, 0.f};

        auto burst = [&](uint32_t stb, int h, float (&acc)[2][4]) {
            #pragma unroll
            for (int jn = 0; jn < 2; jn++)
                #pragma unroll
                for (int q = 0; q < 4; q++) acc[jn][q] = 0.f;
            #pragma unroll
            for (int ks = 0; ks < 4; ks++) {
                uint32_t b0, b1, b2, b3;
                uint32_t addr = stb + rB_off[h] + (((ks * 2 + cb) ^ rB_msk[h]) * 16);
                LDSM4(b0, b1, b2, b3, addr);
                asm volatile(
                    "mma.sync.aligned.m16n8k16.row.col.f32.bf16.bf16.f32 "
                    "{%0,%1,%2,%3}, {%4,%5,%6,%7}, {%8,%9}, {%0,%1,%2,%3};"
                    : "+f"(acc[0][0]), "+f"(acc[0][1]), "+f"(acc[0][2]), "+f"(acc[0][3])
                    : "r"(afr[ks][0]), "r"(afr[ks][1]), "r"(afr[ks][2]), "r"(afr[ks][3]),
                      "r"(b0), "r"(b2));
                asm volatile(
                    "mma.sync.aligned.m16n8k16.row.col.f32.bf16.bf16.f32 "
                    "{%0,%1,%2,%3}, {%4,%5,%6,%7}, {%8,%9}, {%0,%1,%2,%3};"
                    : "+f"(acc[1][0]), "+f"(acc[1][1]), "+f"(acc[1][2]), "+f"(acc[1][3])
                    : "r"(afr[ks][0]), "r"(afr[ks][1]), "r"(afr[ks][2]), "r"(afr[ks][3]),
                      "r"(b1), "r"(b3));
            }
        };
        // epi: cc loaded here (L2-hot; latency hidden by 8.5 warps/SMSP)
        auto epi = [&](float (&acc)[2][4], const float* ct) {
            float2 f0 = __ldg(reinterpret_cast<const float2*>(ct));
            float2 f1 = __ldg(reinterpret_cast<const float2*>(ct + 8));
            uint64_t cc0 = pk2(f0.x, f0.y);
            uint64_t cc1 = pk2(f1.x, f1.y);
            #pragma unroll
            for (int r = 0; r < 2; r++) {        // hf = r (rows g, g+8)
                uint64_t v0 = fma2(pk2(acc[0][r * 2], acc[0][r * 2 + 1]), inv42, cc0);
                uint64_t v1 = fma2(pk2(acc[1][r * 2], acc[1][r * 2 + 1]), inv42, cc1);
                uint32_t a, d;
                upk2(a, d, v0);
                sums[r] += ex2(__uint_as_float(a));
                sums[r] += ex2(__uint_as_float(d));
                upk2(a, d, v1);
                sums[r] += ex2(__uint_as_float(a));
                sums[r] += ex2(__uint_as_float(d));
            }
        };

        for (int it = 0; it < NTILES; it++) {
            const int st = it & 1, r = it >> 1;
            const uint32_t stb = Sb + (uint32_t)st * STAGE;
            mbar_wait(fullA[st], r & 1);

            burst(stb, 0, accA);            // h0 -> accA
            burst(stb, 1, accB);            // h1 -> accB
            if (lane == 0) mbar_arrive(emptyA[st]);   // all LDSMs done; stage free

            const float* ct = gc + it * NT;
            epi(accA, ct);                  // one-burst drain distance
            epi(accB, ct + 16);
        }

        // quad reduce, store to red[]
        #pragma unroll
        for (int r = 0; r < 2; r++) {
            float sv = sums[r];
            sv += __shfl_xor_sync(0xffffffffu, sv, 1);
            sv += __shfl_xor_sync(0xffffffffu, sv, 2);
            if (c == 0) red[wn][wm * 16 + r * 8 + g] = sv;
        }
    }

    __syncthreads();
    if (tid < MT) {
        float tot = red[0][tid] + red[1][tid] + red[2][tid] + red[3][tid];
        g_part[split * MM + m0 + tid] = tot;
    }
    __syncthreads();

    // ---- tail CTA per m-block merges the 23 split sums ----
    if (tid == 0) {
        __threadfence();
        int old = atomicAdd(&g_cnt[blockIdx.x], 1);
        sdone_flag = (old == NSPLIT - 1) ? 1 : 0;
        if (sdone_flag) __threadfence();
    }
    __syncthreads();
    if (sdone_flag) {
        if (tid < MT) {
            float tot = 0.f;
            #pragma unroll
            for (int s = 0; s < NSPLIT; s++) tot += __ldcg(&g_part[s * MM + m0 + tid]);
            // coeff = -ln(50000) - 32*ln(2*pi); row term applied here
            out[m0 + tid] = -69.63184443f
                          + (log2f(tot) - g_RT[m0 + tid]) * 0.6931471805599453f;
        }
        __syncthreads();
        if (tid == 0) g_cnt[blockIdx.x] = 0;   // reset for next graph replay
    }
}

extern "C" void kernel_launch(void* const* d_in, const int* in_sizes, int n_in,
                              void* d_out, int out_size) {
    const float* x  = (const float*)d_in[0];   // [4096, 64]
    const float* X  = (const float*)d_in[1];   // [50000, 64]
    const float* bw = (const float*)d_in[2];   // [1]

    prep_all<<<NPAD / 32 + MM / 32, 256>>>(x, X, bw);   // 1696 blocks

    dim3 grid(MM / MT, NSPLIT);                         // (64, 23)
    kde_main<<<grid, 544>>>(bw, (float*)d_out);
}

// round 14
// speedup vs baseline: 1.1814x; 1.0074x over previous
#include <cuda_runtime.h>
#include <cuda_bf16.h>
#include <cstdint>

// GaussianKernelDensity: out[m] = coeff + logsumexp_n( -||x_m - X_n||^2 / (2 b^2) )
// M=4096, N=50000, D=64.  (tcgen05 unavailable: harness targets plain sm_100)
//  Launch 1: prep_all — pack x,X to bf16; colc = -|X|^2*s, rowt = +|x|^2*s.
//  Launch 2: kde_main — 18 warps/CTA, 2 CTA/SM. Warps 16-17: cp.async
//            producers (64 rows each) filling a 4-STAGE SW128 B ring in
//            DYNAMIC shared memory (72KB/CTA via cudaFuncSetAttribute);
//            deep ring + split producers remove the full-barrier delivery
//            bottleneck. Warps 0-15: 4(M)x4(N) consumers, warp tile 16x32,
//            double accumulators, MUFU ex2 epilogue, cc via __ldg.
//            Row term folded out (applied at final log2).

#define MM 4096
#define NN 50000
#define DD 64
#define NPAD 50176
#define NSPLIT 23
#define CHUNK 2176              // 17 * 128
#define NTILES 17
#define MT 64
#define NT 128
#define STAGE 16384             // 128 rows * 128 B
#define NSTG 4
#define SMEM_DYN (NSTG * STAGE + MT * 128)   // 4 stages + x tile = 73728 B

// device scratch
__device__ __nv_bfloat16 g_Xb[NPAD * DD];
__device__ float         g_CT[NPAD];       // -|X_n|^2 * s  (pad rows: -1000)
__device__ __nv_bfloat16 g_xb[MM * DD];
__device__ float         g_RT[MM];         // +|x_m|^2 * s  (subtracted at end)
__device__ float         g_part[NSPLIT * MM];
__device__ int           g_cnt[MM / MT];

#define LDSM4(r0, r1, r2, r3, addr)                                              \
    asm volatile("ldmatrix.sync.aligned.m8n8.x4.shared.b16 {%0,%1,%2,%3}, [%4];" \
                 : "=r"(r0), "=r"(r1), "=r"(r2), "=r"(r3) : "r"(addr))

__device__ __forceinline__ void cp16(uint32_t dst, const void* src) {
    asm volatile("cp.async.cg.shared.global [%0], [%1], 16;" :: "r"(dst), "l"(src));
}
__device__ __forceinline__ uint32_t smem_u32(const void* p) {
    return (uint32_t)__cvta_generic_to_shared(p);
}
__device__ __forceinline__ void mbar_init(uint32_t a, uint32_t cnt) {
    asm volatile("mbarrier.init.shared.b64 [%0], %1;" :: "r"(a), "r"(cnt) : "memory");
}
__device__ __forceinline__ void mbar_arrive(uint32_t a) {
    asm volatile("mbarrier.arrive.shared.b64 _, [%0];" :: "r"(a) : "memory");
}
__device__ __forceinline__ void cp_async_mbar_arrive(uint32_t a) {
    asm volatile("cp.async.mbarrier.arrive.noinc.shared.b64 [%0];" :: "r"(a) : "memory");
}
__device__ __forceinline__ void mbar_wait(uint32_t a, uint32_t parity) {
    asm volatile(
        "{\n\t.reg .pred P;\n\t"
        "WL_%=:\n\t"
        "mbarrier.try_wait.parity.shared.b64 P, [%0], %1;\n\t"
        "@!P bra WL_%=;\n\t"
        "}" :: "r"(a), "r"(parity) : "memory");
}
__device__ __forceinline__ float ex2(float x) {
    float r;
    asm("ex2.approx.ftz.f32 %0, %1;" : "=f"(r) : "f"(x));
    return r;
}

// ---- packed f32x2 helpers (Blackwell) ----
__device__ __forceinline__ uint64_t pk2(float lo, float hi) {
    uint64_t r;
    asm("mov.b64 %0, {%1, %2};" : "=l"(r) : "f"(lo), "f"(hi));
    return r;
}
__device__ __forceinline__ void upk2(uint32_t& lo, uint32_t& hi, uint64_t v) {
    asm("mov.b64 {%0, %1}, %2;" : "=r"(lo), "=r"(hi) : "l"(v));
}
__device__ __forceinline__ uint64_t fma2(uint64_t a, uint64_t b, uint64_t c) {
    uint64_t d;
    asm("fma.rn.f32x2 %0, %1, %2, %3;" : "=l"(d) : "l"(a), "l"(b), "l"(c));
    return d;
}

// ---------------- prep: pack + fold constants ----------------
__global__ void prep_all(const float* __restrict__ xin,
                         const float* __restrict__ Xin,
                         const float* __restrict__ bw) {
    const float b = bw[0];
    const float inv2 = 1.4426950408889634f / (2.f * b * b);   // log2e / (2 b^2)
    const int blk = blockIdx.x, tid = threadIdx.x;
    const int l8 = tid & 7;

    if (blk < NPAD / 32) {                       // X rows (incl. pad)
        int row = blk * 32 + (tid >> 3);
        uint4 packed = make_uint4(0u, 0u, 0u, 0u);
        __nv_bfloat16* hp = reinterpret_cast<__nv_bfloat16*>(&packed);
        float ss = 0.f;
        if (row < NN) {
            const float4* s4 = reinterpret_cast<const float4*>(Xin + row * DD + l8 * 8);
            float4 a = s4[0], d = s4[1];
            ss = a.x*a.x + a.y*a.y + a.z*a.z + a.w*a.w
               + d.x*d.x + d.y*d.y + d.z*d.z + d.w*d.w;
            hp[0] = __float2bfloat16_rn(a.x); hp[1] = __float2bfloat16_rn(a.y);
            hp[2] = __float2bfloat16_rn(a.z); hp[3] = __float2bfloat16_rn(a.w);
            hp[4] = __float2bfloat16_rn(d.x); hp[5] = __float2bfloat16_rn(d.y);
            hp[6] = __float2bfloat16_rn(d.z); hp[7] = __float2bfloat16_rn(d.w);
        }
        *reinterpret_cast<uint4*>(&g_Xb[row * DD + l8 * 8]) = packed;
        ss += __shfl_xor_sync(0xffffffffu, ss, 1);
        ss += __shfl_xor_sync(0xffffffffu, ss, 2);
        ss += __shfl_xor_sync(0xffffffffu, ss, 4);
        if (l8 == 0) g_CT[row] = (row < NN) ? (-ss * inv2) : -1000.f;
    } else {                                     // x rows
        int row = (blk - NPAD / 32) * 32 + (tid >> 3);
        const float4* s4 = reinterpret_cast<const float4*>(xin + row * DD + l8 * 8);
        float4 a = s4[0], d = s4[1];
        float ss = a.x*a.x + a.y*a.y + a.z*a.z + a.w*a.w
                 + d.x*d.x + d.y*d.y + d.z*d.z + d.w*d.w;
        uint4 packed;
        __nv_bfloat16* hp = reinterpret_cast<__nv_bfloat16*>(&packed);
        hp[0] = __float2bfloat16_rn(a.x); hp[1] = __float2bfloat16_rn(a.y);
        hp[2] = __float2bfloat16_rn(a.z); hp[3] = __float2bfloat16_rn(a.w);
        hp[4] = __float2bfloat16_rn(d.x); hp[5] = __float2bfloat16_rn(d.y);
        hp[6] = __float2bfloat16_rn(d.z); hp[7] = __float2bfloat16_rn(d.w);
        *reinterpret_cast<uint4*>(&g_xb[row * DD + l8 * 8]) = packed;
        ss += __shfl_xor_sync(0xffffffffu, ss, 1);
        ss += __shfl_xor_sync(0xffffffffu, ss, 2);
        ss += __shfl_xor_sync(0xffffffffu, ss, 4);
        if (l8 == 0) g_RT[row] = ss * inv2;      // positive; subtracted at end
    }
}

// ---------------- main: producer/consumer GEMM + MUFU exp2 sum ----------------
__global__ __launch_bounds__(576, 2) void kde_main(const float* __restrict__ bw,
                                                   float* __restrict__ out) {
    extern __shared__ __align__(1024) char dynsmem[];        // 4-stage ring + XS
    char* const S  = dynsmem;                                // 4 * 16KB B ring
    char* const XS = dynsmem + NSTG * STAGE;                 // 8KB x tile
    __shared__ __align__(8) uint64_t mbars[2 * NSTG];        // full[4], empty[4]
    __shared__ float red[4][MT];
    __shared__ int sdone_flag;

    const int tid  = threadIdx.x;
    const int warp = tid >> 5;
    const int lane = tid & 31;

    const int m0    = blockIdx.x * MT;
    const int split = blockIdx.y;
    const int n0    = split * CHUNK;

    const uint32_t Sb = smem_u32(S);
    uint32_t fullA[NSTG], emptyA[NSTG];
    #pragma unroll
    for (int s = 0; s < NSTG; s++) {
        fullA[s]  = smem_u32(&mbars[s]);
        emptyA[s] = smem_u32(&mbars[NSTG + s]);
    }

    if (tid == 0) {
        #pragma unroll
        for (int s = 0; s < NSTG; s++) {
            mbar_init(fullA[s], 64);     // 2 producer warps x 32 lanes (noinc)
            mbar_init(emptyA[s], 16);    // 16 consumer warps (lane 0)
        }
    }

    // first 256 threads stage the x tile, swizzled
    if (tid < 256) {
        int row = tid >> 2, q = tid & 3;
        const uint4* s = reinterpret_cast<const uint4*>(g_xb + (m0 + row) * DD + q * 16);
        uint4 v0 = s[0], v1 = s[1];
        int base = row * 128;
        int msk = row & 7;
        *reinterpret_cast<uint4*>(XS + base + (((2 * q)     ^ msk) * 16)) = v0;
        *reinterpret_cast<uint4*>(XS + base + (((2 * q + 1) ^ msk) * 16)) = v1;
    }
    __syncthreads();   // mbarriers initialized + x tile visible

    if (warp >= 16) {
        // ================= producer warps 16,17 (64 rows each) ============
        const int pr = warp - 16;            // 0: rows 0-63, 1: rows 64-127
        const int r0 = lane >> 3, ch = lane & 7;
        const int qbase = pr * 16;           // q in [qbase, qbase+16)
        const __nv_bfloat16* src = g_Xb + (n0 + qbase * 4 + r0) * DD + ch * 8;
        const uint32_t de  = (uint32_t)(r0 * 128 + ((ch ^ r0) * 16));
        const uint32_t dof = (uint32_t)(r0 * 128 + 512 + ((ch ^ r0 ^ 4) * 16));
        for (int it = 0; it < NTILES; it++) {
            const int st = it & 3;
            if (it >= NSTG) mbar_wait(emptyA[st], ((it >> 2) - 1) & 1);
            const uint32_t base = Sb + (uint32_t)st * STAGE;
            #pragma unroll
            for (int q = 0; q < 16; q += 2) {
                cp16(base + (qbase + q) * 512 + de,  src);  src += 4 * DD;
                cp16(base + (qbase + q) * 512 + dof, src);  src += 4 * DD;
            }
            src += 64 * DD;   // skip the other producer's 64 rows
            cp_async_mbar_arrive(fullA[st]);
        }
    } else {
        // ================= consumer warps 0-15: 4(M) x 4(N), tile 16x32 ====
        const int g = lane >> 2;
        const int c = lane & 3;
        const int wm = warp >> 2;     // 0..3 (M: 16-row group)
        const int wn = warp & 3;      // 0..3 (N: 32-col group)

        const float b    = bw[0];
        const float inv4 = 1.4426950408889634f / (b * b);   // log2e / b^2
        const uint64_t inv42 = pk2(inv4, inv4);

        // A fragments for the whole lifetime: 16 rows, K=64 -> 4 LDSM.x4
        const int lr = (lane & 7) + ((lane >> 3) & 1) * 8;
        const int cb = lane >> 4;
        uint32_t afr[4][4];
        {
            int rowp = wm * 16 + lr;
            uint32_t rb = smem_u32(XS) + rowp * 128;
            int rm = rowp & 7;
            #pragma unroll
            for (int ks = 0; ks < 4; ks++)
                LDSM4(afr[ks][0], afr[ks][1], afr[ks][2], afr[ks][3],
                      rb + (((ks * 2 + cb) ^ rm) * 16));
        }

        uint32_t rB_off[2]; int rB_msk[2];
        #pragma unroll
        for (int h = 0; h < 2; h++) {
            int rowp = wn * 32 + h * 16 + lr;
            rB_off[h] = (uint32_t)(rowp * 128);
            rB_msk[h] = rowp & 7;
        }

        const float* gc = g_CT + n0 + wn * 32 + 2 * c;   // + h*16 + jn*8 + it*NT

        float accA[2][4], accB[2][4];      // [jn][q], one half each
        float sums[2] = {0.f, 0.f};

        auto burst = [&](uint32_t stb, int h, float (&acc)[2][4]) {
            #pragma unroll
            for (int jn = 0; jn < 2; jn++)
                #pragma unroll
                for (int q = 0; q < 4; q++) acc[jn][q] = 0.f;
            #pragma unroll
            for (int ks = 0; ks < 4; ks++) {
                uint32_t b0, b1, b2, b3;
                uint32_t addr = stb + rB_off[h] + (((ks * 2 + cb) ^ rB_msk[h]) * 16);
                LDSM4(b0, b1, b2, b3, addr);
                asm volatile(
                    "mma.sync.aligned.m16n8k16.row.col.f32.bf16.bf16.f32 "
                    "{%0,%1,%2,%3}, {%4,%5,%6,%7}, {%8,%9}, {%0,%1,%2,%3};"
                    : "+f"(acc[0][0]), "+f"(acc[0][1]), "+f"(acc[0][2]), "+f"(acc[0][3])
                    : "r"(afr[ks][0]), "r"(afr[ks][1]), "r"(afr[ks][2]), "r"(afr[ks][3]),
                      "r"(b0), "r"(b2));
                asm volatile(
                    "mma.sync.aligned.m16n8k16.row.col.f32.bf16.bf16.f32 "
                    "{%0,%1,%2,%3}, {%4,%5,%6,%7}, {%8,%9}, {%0,%1,%2,%3};"
                    : "+f"(acc[1][0]), "+f"(acc[1][1]), "+f"(acc[1][2]), "+f"(acc[1][3])
                    : "r"(afr[ks][0]), "r"(afr[ks][1]), "r"(afr[ks][2]), "r"(afr[ks][3]),
                      "r"(b1), "r"(b3));
            }
        };
        // epi: cc loaded here (L2-hot; latency hidden by 9 warps/SMSP)
        auto epi = [&](float (&acc)[2][4], const float* ct) {
            float2 f0 = __ldg(reinterpret_cast<const float2*>(ct));
            float2 f1 = __ldg(reinterpret_cast<const float2*>(ct + 8));
            uint64_t cc0 = pk2(f0.x, f0.y);
            uint64_t cc1 = pk2(f1.x, f1.y);
            #pragma unroll
            for (int r = 0; r < 2; r++) {        // hf = r (rows g, g+8)
                uint64_t v0 = fma2(pk2(acc[0][r * 2], acc[0][r * 2 + 1]), inv42, cc0);
                uint64_t v1 = fma2(pk2(acc[1][r * 2], acc[1][r * 2 + 1]), inv42, cc1);
                uint32_t a, d;
                upk2(a, d, v0);
                sums[r] += ex2(__uint_as_float(a));
                sums[r] += ex2(__uint_as_float(d));
                upk2(a, d, v1);
                sums[r] += ex2(__uint_as_float(a));
                sums[r] += ex2(__uint_as_float(d));
            }
        };

        for (int it = 0; it < NTILES; it++) {
            const int st = it & 3;
            const uint32_t stb = Sb + (uint32_t)st * STAGE;
            mbar_wait(fullA[st], (it >> 2) & 1);

            burst(stb, 0, accA);            // h0 -> accA
            burst(stb, 1, accB);            // h1 -> accB
            if (lane == 0) mbar_arrive(emptyA[st]);   // all LDSMs done; stage free

            const float* ct = gc + it * NT;
            epi(accA, ct);                  // one-burst drain distance
            epi(accB, ct + 16);
        }

        // quad reduce, store to red[]
        #pragma unroll
        for (int r = 0; r < 2; r++) {
            float sv = sums[r];
            sv += __shfl_xor_sync(0xffffffffu, sv, 1);
            sv += __shfl_xor_sync(0xffffffffu, sv, 2);
            if (c == 0) red[wn][wm * 16 + r * 8 + g] = sv;
        }
    }

    __syncthreads();
    if (tid < MT) {
        float tot = red[0][tid] + red[1][tid] + red[2][tid] + red[3][tid];
        g_part[split * MM + m0 + tid] = tot;
    }
    __syncthreads();

    // ---- tail CTA per m-block merges the 23 split sums ----
    if (tid == 0) {
        __threadfence();
        int old = atomicAdd(&g_cnt[blockIdx.x], 1);
        sdone_flag = (old == NSPLIT - 1) ? 1 : 0;
        if (sdone_flag) __threadfence();
    }
    __syncthreads();
    if (sdone_flag) {
        if (tid < MT) {
            float tot = 0.f;
            #pragma unroll
            for (int s = 0; s < NSPLIT; s++) tot += __ldcg(&g_part[s * MM + m0 + tid]);
            // coeff = -ln(50000) - 32*ln(2*pi); row term applied here
            out[m0 + tid] = -69.63184443f
                          + (log2f(tot) - g_RT[m0 + tid]) * 0.6931471805599453f;
        }
        __syncthreads();
        if (tid == 0) g_cnt[blockIdx.x] = 0;   // reset for next graph replay
    }
}

extern "C" void kernel_launch(void* const* d_in, const int* in_sizes, int n_in,
                              void* d_out, int out_size) {
    const float* x  = (const float*)d_in[0];   // [4096, 64]
    const float* X  = (const float*)d_in[1];   // [50000, 64]
    const float* bw = (const float*)d_in[2];   // [1]

    // opt-in to >48KB dynamic smem (idempotent; not an allocation)
    cudaFuncSetAttribute(kde_main, cudaFuncAttributeMaxDynamicSharedMemorySize,
                         SMEM_DYN);

    prep_all<<<NPAD / 32 + MM / 32, 256>>>(x, X, bw);   // 1696 blocks

    dim3 grid(MM / MT, NSPLIT);                         // (64, 23)
    kde_main<<<grid, 576, SMEM_DYN>>>(bw, (float*)d_out);
}